// round 1
// baseline (speedup 1.0000x reference)
#include <cuda_runtime.h>
#include <math.h>

// ---------------- problem constants ----------------
#define NV    5023          // vertices
#define C3    15069         // NV*3
#define NJ    5
#define KPAD  224           // padded K: [0,150) betas | [150,160) 0 | [160,196) pose_feat | [196,224) 0
#define NMAX  2048

// ---------------- device scratch ----------------
__device__ float g_JS[NJ * 3 * 150];   // J_regressor @ shapedirs   [j][kc][l]
__device__ float g_JT[NJ * 3];         // J_regressor @ v_template  [j][kc]
__device__ float g_pvec[NMAX * KPAD];  // per-batch coefficient vector
__device__ float g_Amat[NMAX * NJ * 12]; // per-batch skinning transforms (3x4 per joint)

// ---------------- kernel 0a: zero reduction scratch ----------------
__global__ void k_zero() {
    int t = blockIdx.x * blockDim.x + threadIdx.x;
    if (t < NJ * 3 * 150) g_JS[t] = 0.0f;
    if (t < NJ * 3)       g_JT[t] = 0.0f;
}

// ---------------- kernel 0b: JS = Jr @ shapedirs, JT = Jr @ v_template ----------------
// grid (NJ, 16), 512 threads. v-range split across blockIdx.y, atomicAdd partials.
__global__ void k_js(const float* __restrict__ Jr, const float* __restrict__ SD,
                     const float* __restrict__ VT) {
    int j = blockIdx.x;
    int vb = blockIdx.y * 314;
    int ve = vb + 314; if (ve > NV) ve = NV;
    int t = threadIdx.x;
    if (t < 450) {
        float acc = 0.0f;
        for (int v = vb; v < ve; ++v)
            acc = fmaf(Jr[j * NV + v], SD[v * 450 + t], acc);
        atomicAdd(&g_JS[j * 450 + t], acc);
    } else if (t < 453) {
        int kc = t - 450;
        float acc = 0.0f;
        for (int v = vb; v < ve; ++v)
            acc = fmaf(Jr[j * NV + v], VT[v * 3 + kc], acc);
        atomicAdd(&g_JT[j * 3 + kc], acc);
    }
}

// ---------------- rodrigues (replicates the reference exactly) ----------------
__device__ __forceinline__ void rodr(float x, float y, float z, float* R) {
    float a0 = x + 1e-8f, a1 = y + 1e-8f, a2 = z + 1e-8f;
    float ang = sqrtf(a0 * a0 + a1 * a1 + a2 * a2);
    float inv = 1.0f / ang;
    float rx = x * inv, ry = y * inv, rz = z * inv;
    float s = sinf(ang), c = cosf(ang), t = 1.0f - c;
    R[0] = 1.0f - t * (ry * ry + rz * rz);
    R[1] = t * rx * ry - s * rz;
    R[2] = t * rx * rz + s * ry;
    R[3] = t * rx * ry + s * rz;
    R[4] = 1.0f - t * (rx * rx + rz * rz);
    R[5] = t * ry * rz - s * rx;
    R[6] = t * rx * rz - s * ry;
    R[7] = t * ry * rz + s * rx;
    R[8] = 1.0f - t * (rx * rx + ry * ry);
}

__device__ __forceinline__ void mm3(const float* A, const float* B, float* C) {
#pragma unroll
    for (int r = 0; r < 3; r++)
#pragma unroll
        for (int c = 0; c < 3; c++)
            C[r * 3 + c] = A[r * 3 + 0] * B[0 + c] + A[r * 3 + 1] * B[3 + c] + A[r * 3 + 2] * B[6 + c];
}

// ---------------- kernel 1: per-batch params (one warp per batch) ----------------
__global__ void k_batch(const float* __restrict__ shp, const float* __restrict__ ex,
                        const float* __restrict__ neck, const float* __restrict__ jaw,
                        const float* __restrict__ eye, int N) {
    int b = (blockIdx.x * blockDim.x + threadIdx.x) >> 5;
    int lane = threadIdx.x & 31;
    if (b >= N) return;

    float Jp[15];
#pragma unroll
    for (int i = 0; i < 15; i++) Jp[i] = 0.0f;

    for (int l = lane; l < 150; l += 32) {
        float beta = (l < 100) ? shp[b * 100 + l] : ex[b * 50 + (l - 100)];
        g_pvec[b * KPAD + l] = beta;
#pragma unroll
        for (int jk = 0; jk < 15; jk++)
            Jp[jk] = fmaf(g_JS[jk * 150 + l], beta, Jp[jk]);
    }
    // zero pad + pose-feature region (pf overwritten by lane 0 below)
    for (int i = 150 + lane; i < KPAD; i += 32) g_pvec[b * KPAD + i] = 0.0f;

#pragma unroll
    for (int jk = 0; jk < 15; jk++) {
#pragma unroll
        for (int off = 16; off; off >>= 1)
            Jp[jk] += __shfl_down_sync(0xffffffffu, Jp[jk], off);
    }
    __syncwarp();

    if (lane == 0) {
        float J[5][3];
#pragma unroll
        for (int j = 0; j < 5; j++)
#pragma unroll
            for (int kc = 0; kc < 3; kc++)
                J[j][kc] = Jp[j * 3 + kc] + g_JT[j * 3 + kc];

        float R[5][9];
#pragma unroll
        for (int e = 0; e < 9; e++) R[0][e] = (e == 0 || e == 4 || e == 8) ? 1.0f : 0.0f;
        rodr(neck[b * 3 + 0], neck[b * 3 + 1], neck[b * 3 + 2], R[1]);
        rodr(jaw[b * 3 + 0],  jaw[b * 3 + 1],  jaw[b * 3 + 2],  R[2]);
        rodr(eye[b * 6 + 0],  eye[b * 6 + 1],  eye[b * 6 + 2],  R[3]);
        rodr(eye[b * 6 + 3],  eye[b * 6 + 4],  eye[b * 6 + 5],  R[4]);

        // pose feature (R[1:]-I) row-major -> pvec[160..196)
        float* pf = &g_pvec[b * KPAD + 160];
#pragma unroll
        for (int j = 1; j < 5; j++)
#pragma unroll
            for (int e = 0; e < 9; e++)
                pf[(j - 1) * 9 + e] = R[j][e] - ((e == 0 || e == 4 || e == 8) ? 1.0f : 0.0f);

        // kinematic chain (parents: -1,0,1,1,1)
        float Rg[5][9], tg[5][3];
#pragma unroll
        for (int e = 0; e < 9; e++) Rg[0][e] = R[0][e];
#pragma unroll
        for (int kc = 0; kc < 3; kc++) tg[0][kc] = J[0][kc];
#pragma unroll
        for (int i = 1; i < 5; i++) {
            const int p = (i == 1) ? 0 : 1;
            mm3(Rg[p], R[i], Rg[i]);
            float r0 = J[i][0] - J[p][0], r1 = J[i][1] - J[p][1], r2 = J[i][2] - J[p][2];
#pragma unroll
            for (int r = 0; r < 3; r++)
                tg[i][r] = Rg[p][r * 3 + 0] * r0 + Rg[p][r * 3 + 1] * r1 + Rg[p][r * 3 + 2] * r2 + tg[p][r];
        }
        // A = G with translation corrected by rest-pose joints; store top 3 rows (3x4)
        float* Am = &g_Amat[b * 60];
#pragma unroll
        for (int j = 0; j < 5; j++)
#pragma unroll
            for (int r = 0; r < 3; r++) {
                Am[j * 12 + r * 4 + 0] = Rg[j][r * 3 + 0];
                Am[j * 12 + r * 4 + 1] = Rg[j][r * 3 + 1];
                Am[j * 12 + r * 4 + 2] = Rg[j][r * 3 + 2];
                Am[j * 12 + r * 4 + 3] = tg[j][r]
                    - (Rg[j][r * 3 + 0] * J[j][0] + Rg[j][r * 3 + 1] * J[j][1] + Rg[j][r * 3 + 2] * J[j][2]);
            }
    }
}

// ---------------- kernel 2: fused GEMM (128b x 96cols x K=224) + LBS epilogue ----------------
// block: 256 threads, thread tile 4 batches x 12 cols (4 vertices x 3 comps)
__global__ __launch_bounds__(256) void k_main(const float* __restrict__ SD,
                                              const float* __restrict__ PD,
                                              const float* __restrict__ VT,
                                              const float* __restrict__ W,
                                              float* __restrict__ out, int N) {
    __shared__ float SMEM[7936];
    float* sA = SMEM;            // [128][33]
    float* sB = SMEM + 4224;     // [32][97]

    const int tid = threadIdx.x;
    const int vg = tid & 7;      // 8 vertex-groups (4 vertices each)
    const int bg = tid >> 3;     // 32 batch-groups (4 batches each)
    const int v0 = blockIdx.x * 32;
    const int b0 = blockIdx.y * 128;

    float acc[4][12];
#pragma unroll
    for (int i = 0; i < 4; i++)
#pragma unroll
        for (int m = 0; m < 12; m++) acc[i][m] = 0.0f;

    for (int ch = 0; ch < 7; ++ch) {
        const int kc0 = ch * 32;
        __syncthreads();
        // A tile: 128 rows x 32 k, coalesced (row-contiguous in g_pvec)
#pragma unroll
        for (int i = 0; i < 16; i++) {
            int idx = i * 256 + tid;
            int r = idx >> 5, c = idx & 31;
            int b = b0 + r;
            sA[r * 33 + c] = (b < N) ? g_pvec[b * KPAD + kc0 + c] : 0.0f;
        }
        // B tile: 32 k x 96 cols
        if (ch < 5) {
            // shapedirs region: k-contiguous loads (lane varies k)
#pragma unroll
            for (int i = 0; i < 12; i++) {
                int idx = i * 256 + tid;
                int col = idx >> 5, kk = idx & 31;
                int k = kc0 + kk;
                int v = v0 + col / 3;
                int kc = col - (col / 3) * 3;
                float val = 0.0f;
                if (k < 150 && v < NV) val = SD[v * 450 + kc * 150 + k];
                sB[kk * 97 + col] = val;
            }
        } else {
            // posedirs region: col-contiguous loads (lane varies col)
#pragma unroll
            for (int i = 0; i < 12; i++) {
                int idx = i * 256 + tid;
                int kk = idx / 96, col = idx - kk * 96;
                int pr = kc0 - 160 + kk;
                int cg = v0 * 3 + col;
                float val = 0.0f;
                if (pr < 36 && cg < C3) val = PD[pr * C3 + cg];
                sB[kk * 97 + col] = val;
            }
        }
        __syncthreads();

#pragma unroll 8
        for (int kk = 0; kk < 32; kk++) {
            float a[4];
#pragma unroll
            for (int bi = 0; bi < 4; bi++) a[bi] = sA[(bg * 4 + bi) * 33 + kk];
#pragma unroll
            for (int m = 0; m < 12; m++) {
                float bv = sB[kk * 97 + vg * 12 + m];
#pragma unroll
                for (int bi = 0; bi < 4; bi++)
                    acc[bi][m] = fmaf(a[bi], bv, acc[bi][m]);
            }
        }
    }

    // ---------------- LBS epilogue ----------------
    __syncthreads();
    float* sAm = SMEM;           // 128*60 = 7680
    float* sW  = SMEM + 7680;    // 32*5
    float* sVt = SMEM + 7840;    // 32*3
    for (int i = tid; i < 7680; i += 256) {
        int gi = b0 * 60 + i;
        sAm[i] = (gi < N * 60) ? g_Amat[gi] : 0.0f;
    }
    for (int i = tid; i < 160; i += 256) {
        int gi = v0 * 5 + i;
        sW[i] = (gi < NV * 5) ? W[gi] : 0.0f;
    }
    for (int i = tid; i < 96; i += 256) {
        int gi = v0 * 3 + i;
        sVt[i] = (gi < NV * 3) ? VT[gi] : 0.0f;
    }
    __syncthreads();

#pragma unroll
    for (int bi = 0; bi < 4; bi++) {
        int bl = bg * 4 + bi;
        int b = b0 + bl;
        if (b >= N) continue;
        const float* Ab = &sAm[bl * 60];
        float vp[12];
#pragma unroll
        for (int m = 0; m < 12; m++)
            vp[m] = acc[bi][m] + sVt[(vg * 4 + m / 3) * 3 + (m % 3)];
#pragma unroll
        for (int vi = 0; vi < 4; vi++) {
            int vl = vg * 4 + vi;
            int v = v0 + vl;
            if (v >= NV) continue;
#pragma unroll
            for (int r = 0; r < 3; r++) {
                float s = 0.0f;
#pragma unroll
                for (int j = 0; j < 5; j++) {
                    const float* Ar = Ab + j * 12 + r * 4;
                    float t = fmaf(Ar[0], vp[vi * 3 + 0],
                              fmaf(Ar[1], vp[vi * 3 + 1],
                              fmaf(Ar[2], vp[vi * 3 + 2], Ar[3])));
                    s = fmaf(sW[vl * 5 + j], t, s);
                }
                out[(size_t)b * C3 + v * 3 + r] = s;
            }
        }
    }
}

// ---------------- launch ----------------
extern "C" void kernel_launch(void* const* d_in, const int* in_sizes, int n_in,
                              void* d_out, int out_size) {
    const float* shp  = (const float*)d_in[0];
    const float* ex   = (const float*)d_in[1];
    const float* neck = (const float*)d_in[2];
    const float* jaw  = (const float*)d_in[3];
    const float* eye  = (const float*)d_in[4];
    const float* vt   = (const float*)d_in[5];
    const float* sd   = (const float*)d_in[6];
    const float* pd   = (const float*)d_in[7];
    const float* jr   = (const float*)d_in[8];
    const float* lw   = (const float*)d_in[9];
    int N = in_sizes[0] / 100;
    if (N > NMAX) N = NMAX;

    k_zero<<<9, 256>>>();
    k_js<<<dim3(5, 16), 512>>>(jr, sd, vt);
    k_batch<<<(N + 7) / 8, 256>>>(shp, ex, neck, jaw, eye, N);
    k_main<<<dim3((NV + 31) / 32, (N + 127) / 128), 256>>>(sd, pd, vt, lw, (float*)d_out, N);
}

// round 2
// speedup vs baseline: 1.1693x; 1.1693x over previous
#include <cuda_runtime.h>
#include <math.h>

// ---------------- problem constants ----------------
#define NV    5023          // vertices
#define C3    15069         // NV*3
#define NJ    5
#define KTOT  192           // [0,150) betas | [150,186) pose_feat | [186,192) 0
#define NMAX  2048
#define NCH   6             // 6 chunks of 32

// ---------------- device scratch ----------------
__device__ float g_JS[NJ * 3 * 150];    // J_regressor @ shapedirs
__device__ float g_JT[NJ * 3];          // J_regressor @ v_template
__device__ float g_pvec[NMAX * KTOT];   // per-batch coefficient vector
__device__ float g_Amat[NMAX * NJ * 12];// per-batch skinning transforms (3x4)
__device__ float g_B[C3 * KTOT];        // fused k-major B matrix [col][k]

// ---------------- f32x2 helpers ----------------
__device__ __forceinline__ unsigned long long ffma2(unsigned long long a,
                                                    unsigned long long b,
                                                    unsigned long long c) {
    unsigned long long d;
    asm("fma.rn.f32x2 %0, %1, %2, %3;" : "=l"(d) : "l"(a), "l"(b), "l"(c));
    return d;
}
__device__ __forceinline__ unsigned long long pack2(float x) {
    unsigned long long d;
    asm("mov.b64 %0, {%1, %1};" : "=l"(d) : "f"(x));
    return d;
}
__device__ __forceinline__ void unpack2(unsigned long long v, float& lo, float& hi) {
    asm("mov.b64 {%0, %1}, %2;" : "=f"(lo), "=f"(hi) : "l"(v));
}

// ---------------- kernel 0a: zero reduction scratch ----------------
__global__ void k_zero() {
    int t = blockIdx.x * blockDim.x + threadIdx.x;
    if (t < NJ * 3 * 150) g_JS[t] = 0.0f;
    if (t < NJ * 3)       g_JT[t] = 0.0f;
}

// ---------------- kernel 0b: JS = Jr @ shapedirs, JT = Jr @ v_template ----------------
__global__ void k_js(const float* __restrict__ Jr, const float* __restrict__ SD,
                     const float* __restrict__ VT) {
    int j = blockIdx.x;
    int vb = blockIdx.y * 314;
    int ve = vb + 314; if (ve > NV) ve = NV;
    int t = threadIdx.x;
    if (t < 450) {
        float acc = 0.0f;
        for (int v = vb; v < ve; ++v)
            acc = fmaf(Jr[j * NV + v], SD[v * 450 + t], acc);
        atomicAdd(&g_JS[j * 450 + t], acc);
    } else if (t < 453) {
        int kc = t - 450;
        float acc = 0.0f;
        for (int v = vb; v < ve; ++v)
            acc = fmaf(Jr[j * NV + v], VT[v * 3 + kc], acc);
        atomicAdd(&g_JT[j * 3 + kc], acc);
    }
}

// ---------------- kernel 0c: build fused k-major B matrix ----------------
// g_B[col][k]: k<150 -> shapedirs[v][kc][k]; 150<=k<186 -> posedirs[k-150][col]; else 0
__global__ void k_bmat(const float* __restrict__ SD, const float* __restrict__ PD) {
    long long idx = (long long)blockIdx.x * blockDim.x + threadIdx.x;
    if (idx >= (long long)C3 * KTOT) return;
    int col = (int)(idx / KTOT);
    int k = (int)(idx - (long long)col * KTOT);
    int v = col / 3, kc = col - v * 3;
    float val = 0.0f;
    if (k < 150)       val = SD[v * 450 + kc * 150 + k];
    else if (k < 186)  val = PD[(k - 150) * C3 + col];
    g_B[idx] = val;
}

// ---------------- rodrigues ----------------
__device__ __forceinline__ void rodr(float x, float y, float z, float* R) {
    float a0 = x + 1e-8f, a1 = y + 1e-8f, a2 = z + 1e-8f;
    float ang = sqrtf(a0 * a0 + a1 * a1 + a2 * a2);
    float inv = 1.0f / ang;
    float rx = x * inv, ry = y * inv, rz = z * inv;
    float s = sinf(ang), c = cosf(ang), t = 1.0f - c;
    R[0] = 1.0f - t * (ry * ry + rz * rz);
    R[1] = t * rx * ry - s * rz;
    R[2] = t * rx * rz + s * ry;
    R[3] = t * rx * ry + s * rz;
    R[4] = 1.0f - t * (rx * rx + rz * rz);
    R[5] = t * ry * rz - s * rx;
    R[6] = t * rx * rz - s * ry;
    R[7] = t * ry * rz + s * rx;
    R[8] = 1.0f - t * (rx * rx + ry * ry);
}

__device__ __forceinline__ void mm3(const float* A, const float* B, float* C) {
#pragma unroll
    for (int r = 0; r < 3; r++)
#pragma unroll
        for (int c = 0; c < 3; c++)
            C[r * 3 + c] = A[r * 3 + 0] * B[0 + c] + A[r * 3 + 1] * B[3 + c] + A[r * 3 + 2] * B[6 + c];
}

// ---------------- kernel 1: per-batch params (one warp per batch) ----------------
__global__ void k_batch(const float* __restrict__ shp, const float* __restrict__ ex,
                        const float* __restrict__ neck, const float* __restrict__ jaw,
                        const float* __restrict__ eye, int N) {
    int b = (blockIdx.x * blockDim.x + threadIdx.x) >> 5;
    int lane = threadIdx.x & 31;
    if (b >= N) return;

    float Jp[15];
#pragma unroll
    for (int i = 0; i < 15; i++) Jp[i] = 0.0f;

    for (int l = lane; l < 150; l += 32) {
        float beta = (l < 100) ? shp[b * 100 + l] : ex[b * 50 + (l - 100)];
        g_pvec[b * KTOT + l] = beta;
#pragma unroll
        for (int jk = 0; jk < 15; jk++)
            Jp[jk] = fmaf(g_JS[jk * 150 + l], beta, Jp[jk]);
    }
    for (int i = 150 + lane; i < KTOT; i += 32) g_pvec[b * KTOT + i] = 0.0f;

#pragma unroll
    for (int jk = 0; jk < 15; jk++) {
#pragma unroll
        for (int off = 16; off; off >>= 1)
            Jp[jk] += __shfl_down_sync(0xffffffffu, Jp[jk], off);
    }
    __syncwarp();

    if (lane == 0) {
        float J[5][3];
#pragma unroll
        for (int j = 0; j < 5; j++)
#pragma unroll
            for (int kc = 0; kc < 3; kc++)
                J[j][kc] = Jp[j * 3 + kc] + g_JT[j * 3 + kc];

        float R[5][9];
#pragma unroll
        for (int e = 0; e < 9; e++) R[0][e] = (e == 0 || e == 4 || e == 8) ? 1.0f : 0.0f;
        rodr(neck[b * 3 + 0], neck[b * 3 + 1], neck[b * 3 + 2], R[1]);
        rodr(jaw[b * 3 + 0],  jaw[b * 3 + 1],  jaw[b * 3 + 2],  R[2]);
        rodr(eye[b * 6 + 0],  eye[b * 6 + 1],  eye[b * 6 + 2],  R[3]);
        rodr(eye[b * 6 + 3],  eye[b * 6 + 4],  eye[b * 6 + 5],  R[4]);

        float* pf = &g_pvec[b * KTOT + 150];
#pragma unroll
        for (int j = 1; j < 5; j++)
#pragma unroll
            for (int e = 0; e < 9; e++)
                pf[(j - 1) * 9 + e] = R[j][e] - ((e == 0 || e == 4 || e == 8) ? 1.0f : 0.0f);

        float Rg[5][9], tg[5][3];
#pragma unroll
        for (int e = 0; e < 9; e++) Rg[0][e] = R[0][e];
#pragma unroll
        for (int kc = 0; kc < 3; kc++) tg[0][kc] = J[0][kc];
#pragma unroll
        for (int i = 1; i < 5; i++) {
            const int p = (i == 1) ? 0 : 1;
            mm3(Rg[p], R[i], Rg[i]);
            float r0 = J[i][0] - J[p][0], r1 = J[i][1] - J[p][1], r2 = J[i][2] - J[p][2];
#pragma unroll
            for (int r = 0; r < 3; r++)
                tg[i][r] = Rg[p][r * 3 + 0] * r0 + Rg[p][r * 3 + 1] * r1 + Rg[p][r * 3 + 2] * r2 + tg[p][r];
        }
        float* Am = &g_Amat[b * 60];
#pragma unroll
        for (int j = 0; j < 5; j++)
#pragma unroll
            for (int r = 0; r < 3; r++) {
                Am[j * 12 + r * 4 + 0] = Rg[j][r * 3 + 0];
                Am[j * 12 + r * 4 + 1] = Rg[j][r * 3 + 1];
                Am[j * 12 + r * 4 + 2] = Rg[j][r * 3 + 2];
                Am[j * 12 + r * 4 + 3] = tg[j][r]
                    - (Rg[j][r * 3 + 0] * J[j][0] + Rg[j][r * 3 + 1] * J[j][1] + Rg[j][r * 3 + 2] * J[j][2]);
            }
    }
}

// ---------------- kernel 2: FFMA2 GEMM (128b x 96cols x K=192) + LBS epilogue ----------------
#define SB_STRIDE 100   // 32 k-rows x 100 (16B aligned, cols 0..95 used)
__global__ __launch_bounds__(256) void k_main(const float* __restrict__ VT,
                                              const float* __restrict__ W,
                                              float* __restrict__ out, int N) {
    __shared__ float SMEM[7936];
    float* sA = SMEM;            // [128][33]
    float* sB = SMEM + 4224;     // [32][SB_STRIDE], base byte off 16896 (16B aligned)

    const int tid = threadIdx.x;
    const int vg = tid & 7;      // 8 vertex-groups (4 vertices each)
    const int bg = tid >> 3;     // 32 batch-groups (4 batches each)
    const int v0 = blockIdx.x * 32;
    const int b0 = blockIdx.y * 128;

    unsigned long long acc2[4][6];
#pragma unroll
    for (int i = 0; i < 4; i++)
#pragma unroll
        for (int m = 0; m < 6; m++) acc2[i][m] = 0ULL;

    const float* pA = &sA[(bg * 4) * 33];
    const float* pB = &sB[vg * 12];

    for (int ch = 0; ch < NCH; ++ch) {
        const int kc0 = ch * 32;
        __syncthreads();
        // A tile: 128 rows x 32 k (coalesced along k)
#pragma unroll
        for (int i = 0; i < 16; i++) {
            int idx = i * 256 + tid;
            int r = idx >> 5, c = idx & 31;
            int b = b0 + r;
            sA[r * 33 + c] = (b < N) ? g_pvec[b * KTOT + kc0 + c] : 0.0f;
        }
        // B tile: 96 cols x 32 k from fused k-major g_B (coalesced along k)
#pragma unroll
        for (int i = 0; i < 12; i++) {
            int idx = i * 256 + tid;
            int col = idx >> 5, kk = idx & 31;
            int gc = v0 * 3 + col;
            float val = (gc < C3) ? g_B[(long long)gc * KTOT + kc0 + kk] : 0.0f;
            sB[kk * SB_STRIDE + col] = val;
        }
        __syncthreads();

#pragma unroll 4
        for (int kk = 0; kk < 32; kk++) {
            unsigned long long a2[4];
#pragma unroll
            for (int bi = 0; bi < 4; bi++) a2[bi] = pack2(pA[bi * 33 + kk]);
            const float* pbk = pB + kk * SB_STRIDE;
            ulonglong2 bb0 = *(const ulonglong2*)(pbk + 0);
            ulonglong2 bb1 = *(const ulonglong2*)(pbk + 4);
            ulonglong2 bb2 = *(const ulonglong2*)(pbk + 8);
            unsigned long long bv[6] = {bb0.x, bb0.y, bb1.x, bb1.y, bb2.x, bb2.y};
#pragma unroll
            for (int m = 0; m < 6; m++)
#pragma unroll
                for (int bi = 0; bi < 4; bi++)
                    acc2[bi][m] = ffma2(a2[bi], bv[m], acc2[bi][m]);
        }
    }

    // ---------------- LBS epilogue ----------------
    __syncthreads();
    float* sAm = SMEM;           // 128*60 = 7680
    float* sW  = SMEM + 7680;    // 32*5
    float* sVt = SMEM + 7840;    // 32*3
    for (int i = tid; i < 7680; i += 256) {
        int gi = b0 * 60 + i;
        sAm[i] = (gi < N * 60) ? g_Amat[gi] : 0.0f;
    }
    for (int i = tid; i < 160; i += 256) {
        int gi = v0 * 5 + i;
        sW[i] = (gi < NV * 5) ? W[gi] : 0.0f;
    }
    for (int i = tid; i < 96; i += 256) {
        int gi = v0 * 3 + i;
        sVt[i] = (gi < NV * 3) ? VT[gi] : 0.0f;
    }
    __syncthreads();

#pragma unroll
    for (int bi = 0; bi < 4; bi++) {
        int bl = bg * 4 + bi;
        int b = b0 + bl;
        if (b >= N) continue;
        const float* Ab = &sAm[bl * 60];
        float vp[12];
#pragma unroll
        for (int m = 0; m < 6; m++) {
            float lo, hi;
            unpack2(acc2[bi][m], lo, hi);
            vp[2 * m]     = lo + sVt[(vg * 4 + (2 * m) / 3) * 3 + ((2 * m) % 3)];
            vp[2 * m + 1] = hi + sVt[(vg * 4 + (2 * m + 1) / 3) * 3 + ((2 * m + 1) % 3)];
        }
#pragma unroll
        for (int vi = 0; vi < 4; vi++) {
            int vl = vg * 4 + vi;
            int v = v0 + vl;
            if (v >= NV) continue;
#pragma unroll
            for (int r = 0; r < 3; r++) {
                float s = 0.0f;
#pragma unroll
                for (int j = 0; j < 5; j++) {
                    const float* Ar = Ab + j * 12 + r * 4;
                    float t = fmaf(Ar[0], vp[vi * 3 + 0],
                              fmaf(Ar[1], vp[vi * 3 + 1],
                              fmaf(Ar[2], vp[vi * 3 + 2], Ar[3])));
                    s = fmaf(sW[vl * 5 + j], t, s);
                }
                out[(size_t)b * C3 + v * 3 + r] = s;
            }
        }
    }
}

// ---------------- launch ----------------
extern "C" void kernel_launch(void* const* d_in, const int* in_sizes, int n_in,
                              void* d_out, int out_size) {
    const float* shp  = (const float*)d_in[0];
    const float* ex   = (const float*)d_in[1];
    const float* neck = (const float*)d_in[2];
    const float* jaw  = (const float*)d_in[3];
    const float* eye  = (const float*)d_in[4];
    const float* vt   = (const float*)d_in[5];
    const float* sd   = (const float*)d_in[6];
    const float* pd   = (const float*)d_in[7];
    const float* jr   = (const float*)d_in[8];
    const float* lw   = (const float*)d_in[9];
    int N = in_sizes[0] / 100;
    if (N > NMAX) N = NMAX;

    k_zero<<<9, 256>>>();
    k_js<<<dim3(5, 16), 512>>>(jr, sd, vt);
    {
        long long tot = (long long)C3 * KTOT;
        int blocks = (int)((tot + 255) / 256);
        k_bmat<<<blocks, 256>>>(sd, pd);
    }
    k_batch<<<(N + 7) / 8, 256>>>(shp, ex, neck, jaw, eye, N);
    k_main<<<dim3((NV + 31) / 32, (N + 127) / 128), 256>>>(vt, lw, (float*)d_out, N);
}

// round 4
// speedup vs baseline: 1.7197x; 1.4707x over previous
#include <cuda_runtime.h>
#include <math.h>
#include <stdint.h>

// ---------------- problem constants ----------------
#define NV    5023
#define C3    15069
#define NJ    5
#define KTOT  192           // [0,150) betas | [150,186) pose_feat | [186,192) 0
#define NMAX  2048
#define NCH   6             // k-chunks of 32

// ---------------- device scratch ----------------
__device__ float g_JS[NJ * 3 * 150];
__device__ float g_JT[NJ * 3];
__device__ float g_pvec[NMAX * KTOT];     // tf32-rounded coefficient vectors
__device__ float g_Amat[NMAX * NJ * 12];
__device__ float g_B[C3 * KTOT];          // tf32-rounded fused k-major B [col][k]

// ---------------- helpers ----------------
__device__ __forceinline__ float to_tf32(float x) {
    float r;
    asm("cvt.rna.tf32.f32 %0, %1;" : "=f"(r) : "f"(x));
    return r;
}
__device__ __forceinline__ void mma_tf32_16x8x8(float* d, const uint32_t* a, const uint32_t* b) {
    asm volatile(
        "mma.sync.aligned.m16n8k8.row.col.f32.tf32.tf32.f32 "
        "{%0,%1,%2,%3}, {%4,%5,%6,%7}, {%8,%9}, {%0,%1,%2,%3};"
        : "+f"(d[0]), "+f"(d[1]), "+f"(d[2]), "+f"(d[3])
        : "r"(a[0]), "r"(a[1]), "r"(a[2]), "r"(a[3]), "r"(b[0]), "r"(b[1]));
}

// ---------------- kernel 0a: zero reduction scratch ----------------
__global__ void k_zero() {
    int t = blockIdx.x * blockDim.x + threadIdx.x;
    if (t < NJ * 3 * 150) g_JS[t] = 0.0f;
    if (t < NJ * 3)       g_JT[t] = 0.0f;
}

// ---------------- kernel 0b: JS = Jr @ shapedirs, JT = Jr @ v_template ----------------
__global__ void k_js(const float* __restrict__ Jr, const float* __restrict__ SD,
                     const float* __restrict__ VT) {
    int j = blockIdx.x;
    int vb = blockIdx.y * 314;
    int ve = vb + 314; if (ve > NV) ve = NV;
    int t = threadIdx.x;
    if (t < 450) {
        float acc = 0.0f;
        for (int v = vb; v < ve; ++v)
            acc = fmaf(Jr[j * NV + v], SD[v * 450 + t], acc);
        atomicAdd(&g_JS[j * 450 + t], acc);
    } else if (t < 453) {
        int kc = t - 450;
        float acc = 0.0f;
        for (int v = vb; v < ve; ++v)
            acc = fmaf(Jr[j * NV + v], VT[v * 3 + kc], acc);
        atomicAdd(&g_JT[j * 3 + kc], acc);
    }
}

// ---------------- kernel 0c: build fused k-major tf32 B ----------------
__global__ void k_bmat(const float* __restrict__ SD, const float* __restrict__ PD) {
    int idx = blockIdx.x * blockDim.x + threadIdx.x;
    if (idx >= C3 * KTOT) return;
    int col = idx / KTOT;
    int k = idx - col * KTOT;
    int v = col / 3, kc = col - v * 3;
    float val = 0.0f;
    if (k < 150)      val = SD[v * 450 + kc * 150 + k];
    else if (k < 186) val = PD[(k - 150) * C3 + col];
    g_B[idx] = to_tf32(val);
}

// ---------------- rodrigues / chain ----------------
__device__ __forceinline__ void rodr(float x, float y, float z, float* R) {
    float a0 = x + 1e-8f, a1 = y + 1e-8f, a2 = z + 1e-8f;
    float ang = sqrtf(a0 * a0 + a1 * a1 + a2 * a2);
    float inv = 1.0f / ang;
    float rx = x * inv, ry = y * inv, rz = z * inv;
    float s = sinf(ang), c = cosf(ang), t = 1.0f - c;
    R[0] = 1.0f - t * (ry * ry + rz * rz);
    R[1] = t * rx * ry - s * rz;
    R[2] = t * rx * rz + s * ry;
    R[3] = t * rx * ry + s * rz;
    R[4] = 1.0f - t * (rx * rx + rz * rz);
    R[5] = t * ry * rz - s * rx;
    R[6] = t * rx * rz - s * ry;
    R[7] = t * ry * rz + s * rx;
    R[8] = 1.0f - t * (rx * rx + ry * ry);
}
__device__ __forceinline__ void mm3(const float* A, const float* B, float* C) {
#pragma unroll
    for (int r = 0; r < 3; r++)
#pragma unroll
        for (int c = 0; c < 3; c++)
            C[r * 3 + c] = A[r * 3 + 0] * B[0 + c] + A[r * 3 + 1] * B[3 + c] + A[r * 3 + 2] * B[6 + c];
}

// ---------------- kernel 1: per-batch params (one warp per batch) ----------------
__global__ void k_batch(const float* __restrict__ shp, const float* __restrict__ ex,
                        const float* __restrict__ neck, const float* __restrict__ jaw,
                        const float* __restrict__ eye, int N) {
    int b = (blockIdx.x * blockDim.x + threadIdx.x) >> 5;
    int lane = threadIdx.x & 31;
    if (b >= N) return;

    float Jp[15];
#pragma unroll
    for (int i = 0; i < 15; i++) Jp[i] = 0.0f;

    for (int l = lane; l < 150; l += 32) {
        float beta = (l < 100) ? shp[b * 100 + l] : ex[b * 50 + (l - 100)];
        g_pvec[b * KTOT + l] = to_tf32(beta);
#pragma unroll
        for (int jk = 0; jk < 15; jk++)
            Jp[jk] = fmaf(g_JS[jk * 150 + l], beta, Jp[jk]);
    }
    for (int i = 150 + lane; i < KTOT; i += 32) g_pvec[b * KTOT + i] = 0.0f;

#pragma unroll
    for (int jk = 0; jk < 15; jk++) {
#pragma unroll
        for (int off = 16; off; off >>= 1)
            Jp[jk] += __shfl_down_sync(0xffffffffu, Jp[jk], off);
    }
    __syncwarp();

    if (lane == 0) {
        float J[5][3];
#pragma unroll
        for (int j = 0; j < 5; j++)
#pragma unroll
            for (int kc = 0; kc < 3; kc++)
                J[j][kc] = Jp[j * 3 + kc] + g_JT[j * 3 + kc];

        float R[5][9];
#pragma unroll
        for (int e = 0; e < 9; e++) R[0][e] = (e == 0 || e == 4 || e == 8) ? 1.0f : 0.0f;
        rodr(neck[b * 3 + 0], neck[b * 3 + 1], neck[b * 3 + 2], R[1]);
        rodr(jaw[b * 3 + 0],  jaw[b * 3 + 1],  jaw[b * 3 + 2],  R[2]);
        rodr(eye[b * 6 + 0],  eye[b * 6 + 1],  eye[b * 6 + 2],  R[3]);
        rodr(eye[b * 6 + 3],  eye[b * 6 + 4],  eye[b * 6 + 5],  R[4]);

        float* pf = &g_pvec[b * KTOT + 150];
#pragma unroll
        for (int j = 1; j < 5; j++)
#pragma unroll
            for (int e = 0; e < 9; e++)
                pf[(j - 1) * 9 + e] = to_tf32(R[j][e] - ((e == 0 || e == 4 || e == 8) ? 1.0f : 0.0f));

        float Rg[5][9], tg[5][3];
#pragma unroll
        for (int e = 0; e < 9; e++) Rg[0][e] = R[0][e];
#pragma unroll
        for (int kc = 0; kc < 3; kc++) tg[0][kc] = J[0][kc];
#pragma unroll
        for (int i = 1; i < 5; i++) {
            const int p = (i == 1) ? 0 : 1;
            mm3(Rg[p], R[i], Rg[i]);
            float r0 = J[i][0] - J[p][0], r1 = J[i][1] - J[p][1], r2 = J[i][2] - J[p][2];
#pragma unroll
            for (int r = 0; r < 3; r++)
                tg[i][r] = Rg[p][r * 3 + 0] * r0 + Rg[p][r * 3 + 1] * r1 + Rg[p][r * 3 + 2] * r2 + tg[p][r];
        }
        float* Am = &g_Amat[b * 60];
#pragma unroll
        for (int j = 0; j < 5; j++)
#pragma unroll
            for (int r = 0; r < 3; r++) {
                Am[j * 12 + r * 4 + 0] = Rg[j][r * 3 + 0];
                Am[j * 12 + r * 4 + 1] = Rg[j][r * 3 + 1];
                Am[j * 12 + r * 4 + 2] = Rg[j][r * 3 + 2];
                Am[j * 12 + r * 4 + 3] = tg[j][r]
                    - (Rg[j][r * 3 + 0] * J[j][0] + Rg[j][r * 3 + 1] * J[j][1] + Rg[j][r * 3 + 2] * J[j][2]);
            }
    }
}

// ---------------- kernel 2: mma.sync tf32 GEMM (128x96xK192) + LBS epilogue ----------------
// smem (floats): [0, 4608) sA 128x36 | [4608, 8064) sB 96x36 | [8064, 20864) res 128x100
// epilogue reuse of [0,8064): sAm 7680 | sW 160 | sVt 96
#define SA_F   0
#define SB_F   4608
#define RES_F  8064
#define DYN_BYTES ((8064 + 128 * 100) * 4)   // 83456

__global__ __launch_bounds__(256) void k_main(const float* __restrict__ VT,
                                              const float* __restrict__ W,
                                              float* __restrict__ out, int N) {
    extern __shared__ float SM[];
    float* sA = SM + SA_F;
    float* sB = SM + SB_F;
    float* res = SM + RES_F;

    const int tid = threadIdx.x;
    const int wid = tid >> 5, lane = tid & 31;
    const int q = lane & 3, g = lane >> 2;
    const int wm = wid & 3, wn = wid >> 2;     // 4x2 warp grid
    const int v0 = blockIdx.x * 32;            // 32 vertices -> 96 cols
    const int b0 = blockIdx.y * 128;           // 128 batches

    float acc[2][6][4];
#pragma unroll
    for (int mi = 0; mi < 2; mi++)
#pragma unroll
        for (int ni = 0; ni < 6; ni++)
#pragma unroll
            for (int r = 0; r < 4; r++) acc[mi][ni][r] = 0.0f;

    for (int ch = 0; ch < NCH; ++ch) {
        const int kc0 = ch * 32;
        __syncthreads();
        // A tile: 128 batches x 32 k, coalesced along k
#pragma unroll
        for (int i = 0; i < 16; i++) {
            int idx = i * 256 + tid;
            int r = idx >> 5, c = idx & 31;
            int b = b0 + r;
            sA[r * 36 + c] = (b < N) ? g_pvec[b * KTOT + kc0 + c] : 0.0f;
        }
        // B tile: 96 cols x 32 k, coalesced along k, stored [col][k]
#pragma unroll
        for (int i = 0; i < 12; i++) {
            int idx = i * 256 + tid;
            int col = idx >> 5, kk = idx & 31;
            int gc = v0 * 3 + col;
            sB[col * 36 + kk] = (gc < C3) ? g_B[gc * KTOT + kc0 + kk] : 0.0f;
        }
        __syncthreads();

#pragma unroll
        for (int s = 0; s < 4; s++) {
            const int k0 = s * 8;
            uint32_t a[2][4], b[6][2];
            const float* pA = sA + (wm * 32 + g) * 36 + k0 + q;
#pragma unroll
            for (int mi = 0; mi < 2; mi++) {
                const float* p = pA + mi * 16 * 36;
                a[mi][0] = __float_as_uint(p[0]);
                a[mi][1] = __float_as_uint(p[8 * 36]);
                a[mi][2] = __float_as_uint(p[4]);
                a[mi][3] = __float_as_uint(p[8 * 36 + 4]);
            }
            const float* pB = sB + (wn * 48 + g) * 36 + k0 + q;
#pragma unroll
            for (int ni = 0; ni < 6; ni++) {
                b[ni][0] = __float_as_uint(pB[ni * 8 * 36]);
                b[ni][1] = __float_as_uint(pB[ni * 8 * 36 + 4]);
            }
#pragma unroll
            for (int mi = 0; mi < 2; mi++)
#pragma unroll
                for (int ni = 0; ni < 6; ni++)
                    mma_tf32_16x8x8(acc[mi][ni], a[mi], b[ni]);
        }
    }

    // ---------------- stage GEMM result + epilogue data ----------------
    __syncthreads();
#pragma unroll
    for (int mi = 0; mi < 2; mi++)
#pragma unroll
        for (int ni = 0; ni < 6; ni++)
#pragma unroll
            for (int r = 0; r < 4; r++) {
                int row = wm * 32 + mi * 16 + g + (r >> 1) * 8;
                int col = wn * 48 + ni * 8 + q * 2 + (r & 1);
                res[row * 100 + col] = acc[mi][ni][r];
            }

    float* sAm = SM;            // 7680 floats
    float* sW  = SM + 7680;     // 160
    float* sVt = SM + 7840;     // 96
    for (int i = tid; i < 7680; i += 256) {
        int gi = b0 * 60 + i;
        sAm[i] = (gi < N * 60) ? g_Amat[gi] : 0.0f;
    }
    for (int i = tid; i < 160; i += 256) {
        int gi = v0 * 5 + i;
        sW[i] = (gi < NV * 5) ? W[gi] : 0.0f;
    }
    for (int i = tid; i < 96; i += 256) {
        int gi = v0 * 3 + i;
        sVt[i] = (gi < NV * 3) ? VT[gi] : 0.0f;
    }
    __syncthreads();

    // ---------------- LBS epilogue: thread tile 4 batches x 4 vertices ----------------
    const int vg = tid & 7;     // 8 vertex-groups x 4 vertices
    const int bg = tid >> 3;    // 32 batch-groups x 4 batches
#pragma unroll
    for (int bi = 0; bi < 4; bi++) {
        int bl = bg * 4 + bi;
        int b = b0 + bl;
        if (b >= N) continue;
        const float* Ab = &sAm[bl * 60];
        const float* rp = &res[bl * 100 + vg * 12];
        float vp[12];
#pragma unroll
        for (int m = 0; m < 12; m++)
            vp[m] = rp[m] + sVt[vg * 12 + m];
#pragma unroll
        for (int vi = 0; vi < 4; vi++) {
            int vl = vg * 4 + vi;
            int v = v0 + vl;
            if (v >= NV) continue;
#pragma unroll
            for (int r = 0; r < 3; r++) {
                float s = 0.0f;
#pragma unroll
                for (int j = 0; j < 5; j++) {
                    const float* Ar = Ab + j * 12 + r * 4;
                    float t = fmaf(Ar[0], vp[vi * 3 + 0],
                              fmaf(Ar[1], vp[vi * 3 + 1],
                              fmaf(Ar[2], vp[vi * 3 + 2], Ar[3])));
                    s = fmaf(sW[vl * 5 + j], t, s);
                }
                out[(size_t)b * C3 + v * 3 + r] = s;
            }
        }
    }
}

// ---------------- launch ----------------
extern "C" void kernel_launch(void* const* d_in, const int* in_sizes, int n_in,
                              void* d_out, int out_size) {
    const float* shp  = (const float*)d_in[0];
    const float* ex   = (const float*)d_in[1];
    const float* neck = (const float*)d_in[2];
    const float* jaw  = (const float*)d_in[3];
    const float* eye  = (const float*)d_in[4];
    const float* vt   = (const float*)d_in[5];
    const float* sd   = (const float*)d_in[6];
    const float* pd   = (const float*)d_in[7];
    const float* jr   = (const float*)d_in[8];
    const float* lw   = (const float*)d_in[9];
    int N = in_sizes[0] / 100;
    if (N > NMAX) N = NMAX;

    static int smem_set = 0;
    if (!smem_set) {
        cudaFuncSetAttribute(k_main, cudaFuncAttributeMaxDynamicSharedMemorySize, DYN_BYTES);
        smem_set = 1;
    }

    k_zero<<<9, 256>>>();
    k_js<<<dim3(5, 16), 512>>>(jr, sd, vt);
    k_bmat<<<(C3 * KTOT + 255) / 256, 256>>>(sd, pd);
    k_batch<<<(N + 7) / 8, 256>>>(shp, ex, neck, jaw, eye, N);

    dim3 grid((NV + 31) / 32, (N + 127) / 128);
    k_main<<<grid, 256, DYN_BYTES>>>(vt, lw, (float*)d_out, N);
}

// round 5
// speedup vs baseline: 2.2117x; 1.2861x over previous
#include <cuda_runtime.h>
#include <cuda_fp16.h>
#include <math.h>
#include <stdint.h>

// ---------------- problem constants ----------------
#define NV    5023
#define C3    15069
#define C3PAD 15072         // padded col count for B (multiple of 96)
#define NJ    5
#define KTOT  192           // [0,150) betas | [150,186) pose_feat | [186,192) 0
#define NMAX  2048
#define KC    64            // k-chunk
#define NCH   3

// ---------------- device scratch ----------------
__device__ float g_JS[NJ * 3 * 150];
__device__ float g_JT[NJ * 3];
__device__ __align__(16) __half g_pvec[NMAX * KTOT];   // fp16 coefficient vectors (k-major)
__device__ float g_Amat[NMAX * NJ * 12];
__device__ __align__(16) __half g_B[C3PAD * KTOT];     // fp16 fused k-major B [col][k]

// ---------------- helpers ----------------
__device__ __forceinline__ uint32_t smem_u32(const void* p) {
    uint32_t a;
    asm("{ .reg .u64 t; cvta.to.shared.u64 t, %1; cvt.u32.u64 %0, t; }" : "=r"(a) : "l"(p));
    return a;
}
__device__ __forceinline__ void mma_f16_16x8x16(float* d, const uint32_t* a, const uint32_t* b) {
    asm volatile(
        "mma.sync.aligned.m16n8k16.row.col.f32.f16.f16.f32 "
        "{%0,%1,%2,%3}, {%4,%5,%6,%7}, {%8,%9}, {%0,%1,%2,%3};"
        : "+f"(d[0]), "+f"(d[1]), "+f"(d[2]), "+f"(d[3])
        : "r"(a[0]), "r"(a[1]), "r"(a[2]), "r"(a[3]), "r"(b[0]), "r"(b[1]));
}
#define CP_ASYNC16(dst, src) \
    asm volatile("cp.async.cg.shared.global [%0], [%1], 16;" :: "r"(dst), "l"(src))
#define CP_COMMIT()  asm volatile("cp.async.commit_group;" ::: "memory")
#define CP_WAIT(n)   asm volatile("cp.async.wait_group %0;" :: "n"(n) : "memory")

// ---------------- kernel 0a: zero reduction scratch ----------------
__global__ void k_zero() {
    int t = blockIdx.x * blockDim.x + threadIdx.x;
    if (t < NJ * 3 * 150) g_JS[t] = 0.0f;
    if (t < NJ * 3)       g_JT[t] = 0.0f;
}

// ---------------- kernel 0b: JS = Jr @ shapedirs, JT = Jr @ v_template ----------------
__global__ void k_js(const float* __restrict__ Jr, const float* __restrict__ SD,
                     const float* __restrict__ VT) {
    int j = blockIdx.x;
    int vb = blockIdx.y * 314;
    int ve = vb + 314; if (ve > NV) ve = NV;
    int t = threadIdx.x;
    if (t < 450) {
        float acc = 0.0f;
        for (int v = vb; v < ve; ++v)
            acc = fmaf(Jr[j * NV + v], SD[v * 450 + t], acc);
        atomicAdd(&g_JS[j * 450 + t], acc);
    } else if (t < 453) {
        int kc = t - 450;
        float acc = 0.0f;
        for (int v = vb; v < ve; ++v)
            acc = fmaf(Jr[j * NV + v], VT[v * 3 + kc], acc);
        atomicAdd(&g_JT[j * 3 + kc], acc);
    }
}

// ---------------- kernel 0c: build fused k-major fp16 B (padded) ----------------
__global__ void k_bmat(const float* __restrict__ SD, const float* __restrict__ PD) {
    int idx = blockIdx.x * blockDim.x + threadIdx.x;
    if (idx >= C3PAD * KTOT) return;
    int col = idx / KTOT;
    int k = idx - col * KTOT;
    float val = 0.0f;
    if (col < C3) {
        int v = col / 3, kc = col - v * 3;
        if (k < 150)      val = SD[v * 450 + kc * 150 + k];
        else if (k < 186) val = PD[(k - 150) * C3 + col];
    }
    g_B[idx] = __float2half_rn(val);
}

// ---------------- rodrigues / chain ----------------
__device__ __forceinline__ void rodr(float x, float y, float z, float* R) {
    float a0 = x + 1e-8f, a1 = y + 1e-8f, a2 = z + 1e-8f;
    float ang = sqrtf(a0 * a0 + a1 * a1 + a2 * a2);
    float inv = 1.0f / ang;
    float rx = x * inv, ry = y * inv, rz = z * inv;
    float s = sinf(ang), c = cosf(ang), t = 1.0f - c;
    R[0] = 1.0f - t * (ry * ry + rz * rz);
    R[1] = t * rx * ry - s * rz;
    R[2] = t * rx * rz + s * ry;
    R[3] = t * rx * ry + s * rz;
    R[4] = 1.0f - t * (rx * rx + rz * rz);
    R[5] = t * ry * rz - s * rx;
    R[6] = t * rx * rz - s * ry;
    R[7] = t * ry * rz + s * rx;
    R[8] = 1.0f - t * (rx * rx + ry * ry);
}
__device__ __forceinline__ void mm3(const float* A, const float* B, float* C) {
#pragma unroll
    for (int r = 0; r < 3; r++)
#pragma unroll
        for (int c = 0; c < 3; c++)
            C[r * 3 + c] = A[r * 3 + 0] * B[0 + c] + A[r * 3 + 1] * B[3 + c] + A[r * 3 + 2] * B[6 + c];
}

// ---------------- kernel 1: per-batch params (one warp per batch) ----------------
__global__ void k_batch(const float* __restrict__ shp, const float* __restrict__ ex,
                        const float* __restrict__ neck, const float* __restrict__ jaw,
                        const float* __restrict__ eye, int N) {
    int b = (blockIdx.x * blockDim.x + threadIdx.x) >> 5;
    int lane = threadIdx.x & 31;
    if (b >= N) return;

    float Jp[15];
#pragma unroll
    for (int i = 0; i < 15; i++) Jp[i] = 0.0f;

    for (int l = lane; l < 150; l += 32) {
        float beta = (l < 100) ? shp[b * 100 + l] : ex[b * 50 + (l - 100)];
        g_pvec[b * KTOT + l] = __float2half_rn(beta);
#pragma unroll
        for (int jk = 0; jk < 15; jk++)
            Jp[jk] = fmaf(g_JS[jk * 150 + l], beta, Jp[jk]);
    }
    for (int i = 150 + lane; i < KTOT; i += 32) g_pvec[b * KTOT + i] = __float2half_rn(0.0f);

#pragma unroll
    for (int jk = 0; jk < 15; jk++) {
#pragma unroll
        for (int off = 16; off; off >>= 1)
            Jp[jk] += __shfl_down_sync(0xffffffffu, Jp[jk], off);
    }
    __syncwarp();

    if (lane == 0) {
        float J[5][3];
#pragma unroll
        for (int j = 0; j < 5; j++)
#pragma unroll
            for (int kc = 0; kc < 3; kc++)
                J[j][kc] = Jp[j * 3 + kc] + g_JT[j * 3 + kc];

        float R[5][9];
#pragma unroll
        for (int e = 0; e < 9; e++) R[0][e] = (e == 0 || e == 4 || e == 8) ? 1.0f : 0.0f;
        rodr(neck[b * 3 + 0], neck[b * 3 + 1], neck[b * 3 + 2], R[1]);
        rodr(jaw[b * 3 + 0],  jaw[b * 3 + 1],  jaw[b * 3 + 2],  R[2]);
        rodr(eye[b * 6 + 0],  eye[b * 6 + 1],  eye[b * 6 + 2],  R[3]);
        rodr(eye[b * 6 + 3],  eye[b * 6 + 4],  eye[b * 6 + 5],  R[4]);

        __half* pf = &g_pvec[b * KTOT + 150];
#pragma unroll
        for (int j = 1; j < 5; j++)
#pragma unroll
            for (int e = 0; e < 9; e++)
                pf[(j - 1) * 9 + e] = __float2half_rn(R[j][e] - ((e == 0 || e == 4 || e == 8) ? 1.0f : 0.0f));

        float Rg[5][9], tg[5][3];
#pragma unroll
        for (int e = 0; e < 9; e++) Rg[0][e] = R[0][e];
#pragma unroll
        for (int kc = 0; kc < 3; kc++) tg[0][kc] = J[0][kc];
#pragma unroll
        for (int i = 1; i < 5; i++) {
            const int p = (i == 1) ? 0 : 1;
            mm3(Rg[p], R[i], Rg[i]);
            float r0 = J[i][0] - J[p][0], r1 = J[i][1] - J[p][1], r2 = J[i][2] - J[p][2];
#pragma unroll
            for (int r = 0; r < 3; r++)
                tg[i][r] = Rg[p][r * 3 + 0] * r0 + Rg[p][r * 3 + 1] * r1 + Rg[p][r * 3 + 2] * r2 + tg[p][r];
        }
        float* Am = &g_Amat[b * 60];
#pragma unroll
        for (int j = 0; j < 5; j++)
#pragma unroll
            for (int r = 0; r < 3; r++) {
                Am[j * 12 + r * 4 + 0] = Rg[j][r * 3 + 0];
                Am[j * 12 + r * 4 + 1] = Rg[j][r * 3 + 1];
                Am[j * 12 + r * 4 + 2] = Rg[j][r * 3 + 2];
                Am[j * 12 + r * 4 + 3] = tg[j][r]
                    - (Rg[j][r * 3 + 0] * J[j][0] + Rg[j][r * 3 + 1] * J[j][1] + Rg[j][r * 3 + 2] * J[j][2]);
            }
    }
}

// ---------------- kernel 2: fp16 mma GEMM (128x96xK192, cp.async 2-buf) + LBS ----------------
// GEMM smem (bytes): bufA0 @0 (128x72 half = 18432) | bufB0 @18432 (96x72 = 13824)
//                    bufA1 @32256 | bufB1 @50688 | end 64512
// Epilogue reuse:    res (f32) @0: 128x100x4 = 51200 | sAm @51200 (30720) | sW @81920 (640) | sVt @82560 (384)
#define STRH 72   // half stride per row (36 words)
#define OFF_A0 0
#define OFF_B0 18432
#define OFF_A1 32256
#define OFF_B1 50688
#define DYN_BYTES 83456

__global__ __launch_bounds__(256) void k_main(const float* __restrict__ VT,
                                              const float* __restrict__ W,
                                              float* __restrict__ out, int N) {
    extern __shared__ float SM[];
    const uint32_t sbase = smem_u32(SM);

    const int tid = threadIdx.x;
    const int wid = tid >> 5, lane = tid & 31;
    const int q = lane & 3, g = lane >> 2;
    const int wm = wid & 3, wn = wid >> 2;     // 4x2 warp grid
    const int v0 = blockIdx.x * 32;            // 32 vertices -> 96 cols
    const int b0 = blockIdx.y * 128;           // 128 batches

    const uint32_t offA[2] = {OFF_A0, OFF_A1};
    const uint32_t offB[2] = {OFF_B0, OFF_B1};

    // cp.async index split: A tile 128 rows x 8 segs (1024), B tile 96 x 8 (768)
    const int ar = (tid * 4) >> 3;      // not used; compute per-i below

    // ---- issue loader for chunk ch into buffer bf ----
    auto load_chunk = [&](int ch, int bf) {
        const int kc0 = ch * KC;
#pragma unroll
        for (int i = 0; i < 4; i++) {           // A: 1024 segs
            int idx = i * 256 + tid;
            int r = idx >> 3, s = idx & 7;
            int b = b0 + r; if (b >= N) b = N - 1;
            const __half* src = &g_pvec[b * KTOT + kc0 + s * 8];
            CP_ASYNC16(sbase + offA[bf] + (r * STRH + s * 8) * 2, src);
        }
#pragma unroll
        for (int i = 0; i < 3; i++) {           // B: 768 segs
            int idx = i * 256 + tid;
            int r = idx >> 3, s = idx & 7;
            int gc = v0 * 3 + r;                 // < C3PAD by construction
            const __half* src = &g_B[gc * KTOT + kc0 + s * 8];
            CP_ASYNC16(sbase + offB[bf] + (r * STRH + s * 8) * 2, src);
        }
        CP_COMMIT();
    };

    float acc[2][6][4];
#pragma unroll
    for (int mi = 0; mi < 2; mi++)
#pragma unroll
        for (int ni = 0; ni < 6; ni++)
#pragma unroll
            for (int r = 0; r < 4; r++) acc[mi][ni][r] = 0.0f;

    load_chunk(0, 0);

    for (int ch = 0; ch < NCH; ++ch) {
        const int bf = ch & 1;
        if (ch + 1 < NCH) {
            load_chunk(ch + 1, (ch + 1) & 1);
            CP_WAIT(1);
        } else {
            CP_WAIT(0);
        }
        __syncthreads();

        const uint32_t* wA = (const uint32_t*)((const char*)SM + offA[bf]);
        const uint32_t* wB = (const uint32_t*)((const char*)SM + offB[bf]);

#pragma unroll
        for (int s = 0; s < 4; s++) {           // 4 x k16 steps per 64-k chunk
            const int kw = s * 8;               // k offset in words
            uint32_t a[2][4], b[6][2];
#pragma unroll
            for (int mi = 0; mi < 2; mi++) {
                const uint32_t* p = wA + (wm * 32 + mi * 16 + g) * 36 + kw + q;
                a[mi][0] = p[0];
                a[mi][1] = p[8 * 36];
                a[mi][2] = p[4];
                a[mi][3] = p[8 * 36 + 4];
            }
            const uint32_t* pB = wB + (wn * 48 + g) * 36 + kw + q;
#pragma unroll
            for (int ni = 0; ni < 6; ni++) {
                b[ni][0] = pB[ni * 8 * 36];
                b[ni][1] = pB[ni * 8 * 36 + 4];
            }
#pragma unroll
            for (int mi = 0; mi < 2; mi++)
#pragma unroll
                for (int ni = 0; ni < 6; ni++)
                    mma_f16_16x8x16(acc[mi][ni], a[mi], b[ni]);
        }
        __syncthreads();
    }

    // ---------------- stage GEMM result + epilogue data ----------------
    float* res = SM;                 // 128x100
    float* sAm = SM + 12800;         // 7680 floats
    float* sW  = SM + 20480;         // 160
    float* sVt = SM + 20640;         // 96
#pragma unroll
    for (int mi = 0; mi < 2; mi++)
#pragma unroll
        for (int ni = 0; ni < 6; ni++)
#pragma unroll
            for (int r = 0; r < 4; r++) {
                int row = wm * 32 + mi * 16 + g + (r >> 1) * 8;
                int col = wn * 48 + ni * 8 + q * 2 + (r & 1);
                res[row * 100 + col] = acc[mi][ni][r];
            }

    for (int i = tid; i < 7680; i += 256) {
        int gi = b0 * 60 + i;
        sAm[i] = (gi < N * 60) ? g_Amat[gi] : 0.0f;
    }
    for (int i = tid; i < 160; i += 256) {
        int gi = v0 * 5 + i;
        sW[i] = (gi < NV * 5) ? W[gi] : 0.0f;
    }
    for (int i = tid; i < 96; i += 256) {
        int gi = v0 * 3 + i;
        sVt[i] = (gi < NV * 3) ? VT[gi] : 0.0f;
    }
    __syncthreads();

    // ---------------- LBS epilogue: thread tile 4 batches x 4 vertices ----------------
    const int vg = tid & 7;
    const int bg = tid >> 3;
#pragma unroll
    for (int bi = 0; bi < 4; bi++) {
        int bl = bg * 4 + bi;
        int b = b0 + bl;
        if (b >= N) continue;
        const float* Ab = &sAm[bl * 60];
        const float* rp = &res[bl * 100 + vg * 12];
        float vp[12];
#pragma unroll
        for (int m = 0; m < 12; m++)
            vp[m] = rp[m] + sVt[vg * 12 + m];
#pragma unroll
        for (int vi = 0; vi < 4; vi++) {
            int vl = vg * 4 + vi;
            int v = v0 + vl;
            if (v >= NV) continue;
#pragma unroll
            for (int r = 0; r < 3; r++) {
                float s = 0.0f;
#pragma unroll
                for (int j = 0; j < 5; j++) {
                    const float* Ar = Ab + j * 12 + r * 4;
                    float t = fmaf(Ar[0], vp[vi * 3 + 0],
                              fmaf(Ar[1], vp[vi * 3 + 1],
                              fmaf(Ar[2], vp[vi * 3 + 2], Ar[3])));
                    s = fmaf(sW[vl * 5 + j], t, s);
                }
                out[(size_t)b * C3 + v * 3 + r] = s;
            }
        }
    }
}

// ---------------- launch ----------------
extern "C" void kernel_launch(void* const* d_in, const int* in_sizes, int n_in,
                              void* d_out, int out_size) {
    const float* shp  = (const float*)d_in[0];
    const float* ex   = (const float*)d_in[1];
    const float* neck = (const float*)d_in[2];
    const float* jaw  = (const float*)d_in[3];
    const float* eye  = (const float*)d_in[4];
    const float* vt   = (const float*)d_in[5];
    const float* sd   = (const float*)d_in[6];
    const float* pd   = (const float*)d_in[7];
    const float* jr   = (const float*)d_in[8];
    const float* lw   = (const float*)d_in[9];
    int N = in_sizes[0] / 100;
    if (N > NMAX) N = NMAX;

    static int smem_set = 0;
    if (!smem_set) {
        cudaFuncSetAttribute(k_main, cudaFuncAttributeMaxDynamicSharedMemorySize, DYN_BYTES);
        smem_set = 1;
    }

    k_zero<<<9, 256>>>();
    k_js<<<dim3(5, 16), 512>>>(jr, sd, vt);
    k_bmat<<<(C3PAD * KTOT + 255) / 256, 256>>>(sd, pd);
    k_batch<<<(N + 7) / 8, 256>>>(shp, ex, neck, jaw, eye, N);

    dim3 grid((NV + 31) / 32, (N + 127) / 128);
    k_main<<<grid, 256, DYN_BYTES>>>(vt, lw, (float*)d_out, N);
}

// round 7
// speedup vs baseline: 2.5430x; 1.1498x over previous
#include <cuda_runtime.h>
#include <cuda_fp16.h>
#include <math.h>
#include <stdint.h>

// ---------------- problem constants ----------------
#define NV    5023
#define C3    15069
#define C3PAD 15072
#define NW5   25120          // padded NV*5 (NV*5 = 25115)
#define NJ    5
#define KTOT  192            // [0,150) betas | [150,186) pose_feat | [186,192) 0
#define NMAX  2048
#define KC    64
#define NCH   3

// ---------------- device scratch ----------------
__device__ float g_JS[NJ * 3 * 150];
__device__ float g_JT[NJ * 3];
__device__ __align__(16) __half g_pvec[NMAX * KTOT];
__device__ __align__(16) float g_Amat[NMAX * NJ * 12];
__device__ __align__(16) __half g_B[C3PAD * KTOT];
__device__ __align__(16) float g_Wp[NW5];      // padded lbs_weights
__device__ __align__(16) float g_VTp[C3PAD];   // padded v_template

// ---------------- helpers ----------------
__device__ __forceinline__ uint32_t smem_u32(const void* p) {
    uint32_t a;
    asm("{ .reg .u64 t; cvta.to.shared.u64 t, %1; cvt.u32.u64 %0, t; }" : "=r"(a) : "l"(p));
    return a;
}
__device__ __forceinline__ void mma_f16_16x8x16(float* d, const uint32_t* a, const uint32_t* b) {
    asm volatile(
        "mma.sync.aligned.m16n8k16.row.col.f32.f16.f16.f32 "
        "{%0,%1,%2,%3}, {%4,%5,%6,%7}, {%8,%9}, {%0,%1,%2,%3};"
        : "+f"(d[0]), "+f"(d[1]), "+f"(d[2]), "+f"(d[3])
        : "r"(a[0]), "r"(a[1]), "r"(a[2]), "r"(a[3]), "r"(b[0]), "r"(b[1]));
}
#define CP_ASYNC16(dst, src) \
    asm volatile("cp.async.cg.shared.global [%0], [%1], 16;" :: "r"(dst), "l"(src))
#define CP_COMMIT()  asm volatile("cp.async.commit_group;" ::: "memory")
#define CP_WAIT(n)   asm volatile("cp.async.wait_group %0;" :: "n"(n) : "memory")

// ---------------- kernel 0a: zero reduction scratch ----------------
__global__ void k_zero() {
    int t = blockIdx.x * blockDim.x + threadIdx.x;
    if (t < NJ * 3 * 150) g_JS[t] = 0.0f;
    if (t < NJ * 3)       g_JT[t] = 0.0f;
}

// ---------------- kernel 0b: single-pass JS/JT (all 5 joints per block) ----------------
__global__ void k_js(const float* __restrict__ Jr, const float* __restrict__ SD,
                     const float* __restrict__ VT) {
    __shared__ float sJr[NJ][160];
    int vb = blockIdx.x * 157;
    int ve = vb + 157; if (ve > NV) ve = NV;
    int nv = ve - vb;
    int t = threadIdx.x;
    for (int i = t; i < NJ * 157; i += 512) {
        int j = i / 157, v = i - j * 157;
        sJr[j][v] = (vb + v < NV) ? Jr[j * NV + vb + v] : 0.0f;
    }
    __syncthreads();
    if (t < 450) {
        float acc[NJ] = {0.f, 0.f, 0.f, 0.f, 0.f};
        for (int v = 0; v < nv; ++v) {
            float sd = SD[(vb + v) * 450 + t];
#pragma unroll
            for (int j = 0; j < NJ; j++) acc[j] = fmaf(sJr[j][v], sd, acc[j]);
        }
#pragma unroll
        for (int j = 0; j < NJ; j++) atomicAdd(&g_JS[j * 450 + t], acc[j]);
    } else if (t < 453) {
        int kc = t - 450;
        float acc[NJ] = {0.f, 0.f, 0.f, 0.f, 0.f};
        for (int v = 0; v < nv; ++v) {
            float vt = VT[(vb + v) * 3 + kc];
#pragma unroll
            for (int j = 0; j < NJ; j++) acc[j] = fmaf(sJr[j][v], vt, acc[j]);
        }
#pragma unroll
        for (int j = 0; j < NJ; j++) atomicAdd(&g_JT[j * 3 + kc], acc[j]);
    }
}

// ---------------- kernel 0c: fused k-major fp16 B (padded) + padded W/VT copies ----------------
__global__ void k_bmat(const float* __restrict__ SD, const float* __restrict__ PD,
                       const float* __restrict__ W, const float* __restrict__ VT) {
    int idx = blockIdx.x * blockDim.x + threadIdx.x;
    if (idx < NW5)   g_Wp[idx]  = (idx < NV * 5) ? W[idx]  : 0.0f;
    if (idx < C3PAD) g_VTp[idx] = (idx < C3)     ? VT[idx] : 0.0f;
    if (idx >= C3PAD * KTOT) return;
    int col = idx / KTOT;
    int k = idx - col * KTOT;
    float val = 0.0f;
    if (col < C3) {
        int v = col / 3, kc = col - v * 3;
        if (k < 150)      val = SD[v * 450 + kc * 150 + k];
        else if (k < 186) val = PD[(k - 150) * C3 + col];
    }
    g_B[idx] = __float2half_rn(val);
}

// ---------------- rodrigues / chain ----------------
__device__ __forceinline__ void rodr(float x, float y, float z, float* R) {
    float a0 = x + 1e-8f, a1 = y + 1e-8f, a2 = z + 1e-8f;
    float ang = sqrtf(a0 * a0 + a1 * a1 + a2 * a2);
    float inv = 1.0f / ang;
    float rx = x * inv, ry = y * inv, rz = z * inv;
    float s = sinf(ang), c = cosf(ang), t = 1.0f - c;
    R[0] = 1.0f - t * (ry * ry + rz * rz);
    R[1] = t * rx * ry - s * rz;
    R[2] = t * rx * rz + s * ry;
    R[3] = t * rx * ry + s * rz;
    R[4] = 1.0f - t * (rx * rx + rz * rz);
    R[5] = t * ry * rz - s * rx;
    R[6] = t * rx * rz - s * ry;
    R[7] = t * ry * rz + s * rx;
    R[8] = 1.0f - t * (rx * rx + ry * ry);
}
__device__ __forceinline__ void mm3(const float* A, const float* B, float* C) {
#pragma unroll
    for (int r = 0; r < 3; r++)
#pragma unroll
        for (int c = 0; c < 3; c++)
            C[r * 3 + c] = A[r * 3 + 0] * B[0 + c] + A[r * 3 + 1] * B[3 + c] + A[r * 3 + 2] * B[6 + c];
}

// ---------------- kernel 1: per-batch params (one warp per batch, smem JS) ----------------
__global__ __launch_bounds__(256) void k_batch(const float* __restrict__ shp, const float* __restrict__ ex,
                        const float* __restrict__ neck, const float* __restrict__ jaw,
                        const float* __restrict__ eye, int N) {
    __shared__ float sJS[2250];
    __shared__ float sJT[15];
    int tid = threadIdx.x;
    for (int i = tid; i < 2250; i += 256) sJS[i] = g_JS[i];
    if (tid < 15) sJT[tid] = g_JT[tid];
    __syncthreads();

    int b = (blockIdx.x * blockDim.x + tid) >> 5;
    int lane = tid & 31;
    if (b >= N) return;

    float Jp[15];
#pragma unroll
    for (int i = 0; i < 15; i++) Jp[i] = 0.0f;

    for (int l = lane; l < 150; l += 32) {
        float beta = (l < 100) ? shp[b * 100 + l] : ex[b * 50 + (l - 100)];
        g_pvec[b * KTOT + l] = __float2half_rn(beta);
#pragma unroll
        for (int jk = 0; jk < 15; jk++)
            Jp[jk] = fmaf(sJS[jk * 150 + l], beta, Jp[jk]);
    }
    for (int i = 150 + lane; i < KTOT; i += 32) g_pvec[b * KTOT + i] = __float2half_rn(0.0f);

#pragma unroll
    for (int jk = 0; jk < 15; jk++) {
#pragma unroll
        for (int off = 16; off; off >>= 1)
            Jp[jk] += __shfl_down_sync(0xffffffffu, Jp[jk], off);
    }
    __syncwarp();

    if (lane == 0) {
        float J[5][3];
#pragma unroll
        for (int j = 0; j < 5; j++)
#pragma unroll
            for (int kc = 0; kc < 3; kc++)
                J[j][kc] = Jp[j * 3 + kc] + sJT[j * 3 + kc];

        float R[5][9];
#pragma unroll
        for (int e = 0; e < 9; e++) R[0][e] = (e == 0 || e == 4 || e == 8) ? 1.0f : 0.0f;
        rodr(neck[b * 3 + 0], neck[b * 3 + 1], neck[b * 3 + 2], R[1]);
        rodr(jaw[b * 3 + 0],  jaw[b * 3 + 1],  jaw[b * 3 + 2],  R[2]);
        rodr(eye[b * 6 + 0],  eye[b * 6 + 1],  eye[b * 6 + 2],  R[3]);
        rodr(eye[b * 6 + 3],  eye[b * 6 + 4],  eye[b * 6 + 5],  R[4]);

        __half* pf = &g_pvec[b * KTOT + 150];
#pragma unroll
        for (int j = 1; j < 5; j++)
#pragma unroll
            for (int e = 0; e < 9; e++)
                pf[(j - 1) * 9 + e] = __float2half_rn(R[j][e] - ((e == 0 || e == 4 || e == 8) ? 1.0f : 0.0f));

        float Rg[5][9], tg[5][3];
#pragma unroll
        for (int e = 0; e < 9; e++) Rg[0][e] = R[0][e];
#pragma unroll
        for (int kc = 0; kc < 3; kc++) tg[0][kc] = J[0][kc];
#pragma unroll
        for (int i = 1; i < 5; i++) {
            const int p = (i == 1) ? 0 : 1;
            mm3(Rg[p], R[i], Rg[i]);
            float r0 = J[i][0] - J[p][0], r1 = J[i][1] - J[p][1], r2 = J[i][2] - J[p][2];
#pragma unroll
            for (int r = 0; r < 3; r++)
                tg[i][r] = Rg[p][r * 3 + 0] * r0 + Rg[p][r * 3 + 1] * r1 + Rg[p][r * 3 + 2] * r2 + tg[p][r];
        }
        float* Am = &g_Amat[b * 60];
#pragma unroll
        for (int j = 0; j < 5; j++)
#pragma unroll
            for (int r = 0; r < 3; r++) {
                Am[j * 12 + r * 4 + 0] = Rg[j][r * 3 + 0];
                Am[j * 12 + r * 4 + 1] = Rg[j][r * 3 + 1];
                Am[j * 12 + r * 4 + 2] = Rg[j][r * 3 + 2];
                Am[j * 12 + r * 4 + 3] = tg[j][r]
                    - (Rg[j][r * 3 + 0] * J[j][0] + Rg[j][r * 3 + 1] * J[j][1] + Rg[j][r * 3 + 2] * J[j][2]);
            }
    }
}

// ---------------- kernel 2: fp16 mma GEMM + in-place LBS + coalesced stores ----------------
// GEMM bytes: bufA0@0 (18432) | bufB0@18432 (13824) | bufA1@32256 | bufB1@50688 | end 64512
// Epi region (dedicated, cp.async-prefetched): sAm@64512 (30720) | sW@95232 (640) | sVt@95872 (384)
// res (f32 128x100) reuses [0, 51200) after GEMM.
#define STRH 72
#define OFF_A0 0
#define OFF_B0 18432
#define OFF_A1 32256
#define OFF_B1 50688
#define OFF_EAM 64512
#define OFF_EW  95232
#define OFF_EVT 95872
#define DYN_BYTES 96256

__global__ __launch_bounds__(256) void k_main(float* __restrict__ out, int N) {
    extern __shared__ float SM[];
    const uint32_t sbase = smem_u32(SM);

    const int tid = threadIdx.x;
    const int wid = tid >> 5, lane = tid & 31;
    const int q = lane & 3, g = lane >> 2;
    const int wm = wid & 3, wn = wid >> 2;
    const int v0 = blockIdx.x * 32;
    const int b0 = blockIdx.y * 128;

    const uint32_t offA[2] = {OFF_A0, OFF_A1};
    const uint32_t offB[2] = {OFF_B0, OFF_B1};

    auto load_chunk = [&](int ch, int bf) {
#pragma unroll
        for (int i = 0; i < 4; i++) {
            int idx = i * 256 + tid;
            int r = idx >> 3, s = idx & 7;
            int b = b0 + r; if (b >= N) b = N - 1;
            const __half* src = &g_pvec[b * KTOT + ch * KC + s * 8];
            CP_ASYNC16(sbase + offA[bf] + (r * STRH + s * 8) * 2, src);
        }
#pragma unroll
        for (int i = 0; i < 3; i++) {
            int idx = i * 256 + tid;
            int r = idx >> 3, s = idx & 7;
            const __half* src = &g_B[(v0 * 3 + r) * KTOT + ch * KC + s * 8];
            CP_ASYNC16(sbase + offB[bf] + (r * STRH + s * 8) * 2, src);
        }
    };

    // epilogue operand prefetch (joins chunk 0's commit group); padded sources -> aligned, in-bounds
    {
#pragma unroll
        for (int i = 0; i < 8; i++) {                 // sAm: 1920 segs (exact: 128*60 floats)
            int seg = i * 256 + tid;
            if (seg < 1920) {
                int gi = b0 * 60 + seg * 4;
                if (gi + 4 > N * 60) gi = N * 60 - 4;  // multiple of 4 -> aligned
                CP_ASYNC16(sbase + OFF_EAM + seg * 16, &g_Amat[gi]);
            }
        }
        if (tid < 40)                                  // sW: 160 floats from padded g_Wp
            CP_ASYNC16(sbase + OFF_EW + tid * 16, &g_Wp[v0 * 5 + tid * 4]);
        if (tid < 24)                                  // sVt: 96 floats from padded g_VTp
            CP_ASYNC16(sbase + OFF_EVT + tid * 16, &g_VTp[v0 * 3 + tid * 4]);
    }
    load_chunk(0, 0);
    CP_COMMIT();

    float acc[2][6][4];
#pragma unroll
    for (int mi = 0; mi < 2; mi++)
#pragma unroll
        for (int ni = 0; ni < 6; ni++)
#pragma unroll
            for (int r = 0; r < 4; r++) acc[mi][ni][r] = 0.0f;

    for (int ch = 0; ch < NCH; ++ch) {
        const int bf = ch & 1;
        if (ch + 1 < NCH) {
            load_chunk(ch + 1, (ch + 1) & 1);
            CP_COMMIT();
            CP_WAIT(1);
        } else {
            CP_WAIT(0);
        }
        __syncthreads();

        const uint32_t* wA = (const uint32_t*)((const char*)SM + offA[bf]);
        const uint32_t* wB = (const uint32_t*)((const char*)SM + offB[bf]);

#pragma unroll
        for (int s = 0; s < 4; s++) {
            const int kw = s * 8;
            uint32_t a[2][4], b[6][2];
#pragma unroll
            for (int mi = 0; mi < 2; mi++) {
                const uint32_t* p = wA + (wm * 32 + mi * 16 + g) * 36 + kw + q;
                a[mi][0] = p[0];
                a[mi][1] = p[8 * 36];
                a[mi][2] = p[4];
                a[mi][3] = p[8 * 36 + 4];
            }
            const uint32_t* pB = wB + (wn * 48 + g) * 36 + kw + q;
#pragma unroll
            for (int ni = 0; ni < 6; ni++) {
                b[ni][0] = pB[ni * 8 * 36];
                b[ni][1] = pB[ni * 8 * 36 + 4];
            }
#pragma unroll
            for (int mi = 0; mi < 2; mi++)
#pragma unroll
                for (int ni = 0; ni < 6; ni++)
                    mma_f16_16x8x16(acc[mi][ni], a[mi], b[ni]);
        }
        __syncthreads();
    }

    // ---------------- stage GEMM result ----------------
    float* res = SM;                         // 128x100 f32
    float* sAm = (float*)((char*)SM + OFF_EAM);
    float* sW  = (float*)((char*)SM + OFF_EW);
    float* sVt = (float*)((char*)SM + OFF_EVT);
#pragma unroll
    for (int mi = 0; mi < 2; mi++)
#pragma unroll
        for (int ni = 0; ni < 6; ni++)
#pragma unroll
            for (int r = 0; r < 4; r++) {
                int row = wm * 32 + mi * 16 + g + (r >> 1) * 8;
                int col = wn * 48 + ni * 8 + q * 2 + (r & 1);
                res[row * 100 + col] = acc[mi][ni][r];
            }
    __syncthreads();

    // ---------------- in-place LBS (thread tile 4 batches x 4 vertices) ----------------
    const int vg = tid & 7;
    const int bg = tid >> 3;
#pragma unroll
    for (int bi = 0; bi < 4; bi++) {
        int bl = bg * 4 + bi;
        const float* Ab = &sAm[bl * 60];
        float* rp = &res[bl * 100 + vg * 12];
        float vp[12];
#pragma unroll
        for (int m = 0; m < 12; m++)
            vp[m] = rp[m] + sVt[vg * 12 + m];
#pragma unroll
        for (int vi = 0; vi < 4; vi++) {
            int vl = vg * 4 + vi;
#pragma unroll
            for (int r = 0; r < 3; r++) {
                float s = 0.0f;
#pragma unroll
                for (int j = 0; j < 5; j++) {
                    const float* Ar = Ab + j * 12 + r * 4;
                    float t = fmaf(Ar[0], vp[vi * 3 + 0],
                              fmaf(Ar[1], vp[vi * 3 + 1],
                              fmaf(Ar[2], vp[vi * 3 + 2], Ar[3])));
                    s = fmaf(sW[vl * 5 + j], t, s);
                }
                rp[vi * 3 + r] = s;
            }
        }
    }
    __syncthreads();

    // ---------------- coalesced store ----------------
    const int cmax = C3 - v0 * 3;            // valid cols in this v-tile
#pragma unroll
    for (int i = 0; i < 48; i++) {
        int idx = i * 256 + tid;
        int bl = idx / 96, c = idx - bl * 96;
        int b = b0 + bl;
        if (b < N && c < cmax)
            out[(size_t)b * C3 + v0 * 3 + c] = res[bl * 100 + c];
    }
}

// ---------------- launch ----------------
extern "C" void kernel_launch(void* const* d_in, const int* in_sizes, int n_in,
                              void* d_out, int out_size) {
    const float* shp  = (const float*)d_in[0];
    const float* ex   = (const float*)d_in[1];
    const float* neck = (const float*)d_in[2];
    const float* jaw  = (const float*)d_in[3];
    const float* eye  = (const float*)d_in[4];
    const float* vt   = (const float*)d_in[5];
    const float* sd   = (const float*)d_in[6];
    const float* pd   = (const float*)d_in[7];
    const float* jr   = (const float*)d_in[8];
    const float* lw   = (const float*)d_in[9];
    int N = in_sizes[0] / 100;
    if (N > NMAX) N = NMAX;

    static int smem_set = 0;
    if (!smem_set) {
        cudaFuncSetAttribute(k_main, cudaFuncAttributeMaxDynamicSharedMemorySize, DYN_BYTES);
        smem_set = 1;
    }

    k_zero<<<9, 256>>>();
    k_js<<<32, 512>>>(jr, sd, vt);
    k_bmat<<<(C3PAD * KTOT + 255) / 256, 256>>>(sd, pd, lw, vt);
    k_batch<<<(N + 7) / 8, 256>>>(shp, ex, neck, jaw, eye, N);

    dim3 grid((NV + 31) / 32, (N + 127) / 128);
    k_main<<<grid, 256, DYN_BYTES>>>((float*)d_out, N);
}

// round 8
// speedup vs baseline: 3.5772x; 1.4067x over previous
#include <cuda_runtime.h>
#include <cuda_fp16.h>
#include <math.h>
#include <stdint.h>

// ---------------- problem constants ----------------
#define NV    5023
#define C3    15069
#define C3PAD 15072
#define NW5   25120          // padded NV*5
#define NJ    5
#define KTOT  192            // [0,150) betas | [150,186) pose_feat | [186,192) 0
#define NMAX  2048
#define KC    64
#define NCH   3

// ---------------- device scratch ----------------
__device__ float g_JS[NJ * 3 * 150];
__device__ float g_JT[NJ * 3];
__device__ __align__(16) __half g_pvec[NMAX * KTOT];
// g_Amat: batch-PAIR interleaved: [pair][element 0..59][2 batches]
__device__ __align__(16) float g_Amat[NMAX * NJ * 12];
__device__ __align__(16) __half g_B[C3PAD * KTOT];
__device__ __align__(16) float g_Wp[NW5];
__device__ __align__(16) float g_VTp[C3PAD];

// ---------------- helpers ----------------
__device__ __forceinline__ uint32_t smem_u32(const void* p) {
    uint32_t a;
    asm("{ .reg .u64 t; cvta.to.shared.u64 t, %1; cvt.u32.u64 %0, t; }" : "=r"(a) : "l"(p));
    return a;
}
__device__ __forceinline__ void mma_f16_16x8x16(float* d, const uint32_t* a, const uint32_t* b) {
    asm volatile(
        "mma.sync.aligned.m16n8k16.row.col.f32.f16.f16.f32 "
        "{%0,%1,%2,%3}, {%4,%5,%6,%7}, {%8,%9}, {%0,%1,%2,%3};"
        : "+f"(d[0]), "+f"(d[1]), "+f"(d[2]), "+f"(d[3])
        : "r"(a[0]), "r"(a[1]), "r"(a[2]), "r"(a[3]), "r"(b[0]), "r"(b[1]));
}
__device__ __forceinline__ unsigned long long fma2(unsigned long long a,
                                                   unsigned long long b,
                                                   unsigned long long c) {
    unsigned long long d;
    asm("fma.rn.f32x2 %0, %1, %2, %3;" : "=l"(d) : "l"(a), "l"(b), "l"(c));
    return d;
}
__device__ __forceinline__ unsigned long long add2(unsigned long long a, unsigned long long b) {
    unsigned long long d;
    asm("add.rn.f32x2 %0, %1, %2;" : "=l"(d) : "l"(a), "l"(b));
    return d;
}
__device__ __forceinline__ unsigned long long packb(float x) {       // broadcast
    unsigned long long d;
    asm("mov.b64 %0, {%1, %1};" : "=l"(d) : "f"(x));
    return d;
}
__device__ __forceinline__ unsigned long long packp(float lo, float hi) {
    unsigned long long d;
    asm("mov.b64 %0, {%1, %2};" : "=l"(d) : "f"(lo), "f"(hi));
    return d;
}
__device__ __forceinline__ void unpk(unsigned long long v, float& lo, float& hi) {
    asm("mov.b64 {%0, %1}, %2;" : "=f"(lo), "=f"(hi) : "l"(v));
}
#define CP_ASYNC16(dst, src) \
    asm volatile("cp.async.cg.shared.global [%0], [%1], 16;" :: "r"(dst), "l"(src))
#define CP_COMMIT()  asm volatile("cp.async.commit_group;" ::: "memory")
#define CP_WAIT(n)   asm volatile("cp.async.wait_group %0;" :: "n"(n) : "memory")

// ---------------- kernel 0a: zero reduction scratch ----------------
__global__ void k_zero() {
    int t = blockIdx.x * blockDim.x + threadIdx.x;
    if (t < NJ * 3 * 150) g_JS[t] = 0.0f;
    if (t < NJ * 3)       g_JT[t] = 0.0f;
}

// ---------------- kernel 0b: merged JS/JT reduction + fused B build + pads ----------------
__global__ void k_prep(const float* __restrict__ Jr, const float* __restrict__ SD,
                       const float* __restrict__ PD, const float* __restrict__ VT,
                       const float* __restrict__ W) {
    if (blockIdx.x < 32) {
        __shared__ float sJr[NJ][160];
        int vb = blockIdx.x * 157;
        int ve = vb + 157; if (ve > NV) ve = NV;
        int nv = ve - vb;
        int t = threadIdx.x;
        for (int i = t; i < NJ * 157; i += 512) {
            int j = i / 157, v = i - j * 157;
            sJr[j][v] = (vb + v < NV) ? Jr[j * NV + vb + v] : 0.0f;
        }
        __syncthreads();
        if (t < 450) {
            float acc[NJ] = {0.f, 0.f, 0.f, 0.f, 0.f};
            for (int v = 0; v < nv; ++v) {
                float sd = SD[(vb + v) * 450 + t];
#pragma unroll
                for (int j = 0; j < NJ; j++) acc[j] = fmaf(sJr[j][v], sd, acc[j]);
            }
#pragma unroll
            for (int j = 0; j < NJ; j++) atomicAdd(&g_JS[j * 450 + t], acc[j]);
        } else if (t < 453) {
            int kc = t - 450;
            float acc[NJ] = {0.f, 0.f, 0.f, 0.f, 0.f};
            for (int v = 0; v < nv; ++v) {
                float vt = VT[(vb + v) * 3 + kc];
#pragma unroll
                for (int j = 0; j < NJ; j++) acc[j] = fmaf(sJr[j][v], vt, acc[j]);
            }
#pragma unroll
            for (int j = 0; j < NJ; j++) atomicAdd(&g_JT[j * 3 + kc], acc[j]);
        }
    } else {
        int idx = (blockIdx.x - 32) * 512 + threadIdx.x;
        if (idx < NW5)   g_Wp[idx]  = (idx < NV * 5) ? W[idx]  : 0.0f;
        if (idx < C3PAD) g_VTp[idx] = (idx < C3)     ? VT[idx] : 0.0f;
        if (idx >= C3PAD * KTOT) return;
        int col = idx / KTOT;
        int k = idx - col * KTOT;
        float val = 0.0f;
        if (col < C3) {
            int v = col / 3, kc = col - v * 3;
            if (k < 150)      val = SD[v * 450 + kc * 150 + k];
            else if (k < 186) val = PD[(k - 150) * C3 + col];
        }
        g_B[idx] = __float2half_rn(val);
    }
}

// ---------------- rodrigues / chain ----------------
__device__ __forceinline__ void rodr(float x, float y, float z, float* R) {
    float a0 = x + 1e-8f, a1 = y + 1e-8f, a2 = z + 1e-8f;
    float ang = sqrtf(a0 * a0 + a1 * a1 + a2 * a2);
    float inv = 1.0f / ang;
    float rx = x * inv, ry = y * inv, rz = z * inv;
    float s = sinf(ang), c = cosf(ang), t = 1.0f - c;
    R[0] = 1.0f - t * (ry * ry + rz * rz);
    R[1] = t * rx * ry - s * rz;
    R[2] = t * rx * rz + s * ry;
    R[3] = t * rx * ry + s * rz;
    R[4] = 1.0f - t * (rx * rx + rz * rz);
    R[5] = t * ry * rz - s * rx;
    R[6] = t * rx * rz - s * ry;
    R[7] = t * ry * rz + s * rx;
    R[8] = 1.0f - t * (rx * rx + ry * ry);
}
__device__ __forceinline__ void mm3(const float* A, const float* B, float* C) {
#pragma unroll
    for (int r = 0; r < 3; r++)
#pragma unroll
        for (int c = 0; c < 3; c++)
            C[r * 3 + c] = A[r * 3 + 0] * B[0 + c] + A[r * 3 + 1] * B[3 + c] + A[r * 3 + 2] * B[6 + c];
}

// ---------------- kernel 1: per-batch params (one warp per batch, smem JS) ----------------
__global__ __launch_bounds__(256) void k_batch(const float* __restrict__ shp, const float* __restrict__ ex,
                        const float* __restrict__ neck, const float* __restrict__ jaw,
                        const float* __restrict__ eye, int N) {
    __shared__ float sJS[2250];
    __shared__ float sJT[15];
    int tid = threadIdx.x;
    for (int i = tid; i < 2250; i += 256) sJS[i] = g_JS[i];
    if (tid < 15) sJT[tid] = g_JT[tid];
    __syncthreads();

    int b = (blockIdx.x * blockDim.x + tid) >> 5;
    int lane = tid & 31;
    if (b >= N) return;

    float Jp[15];
#pragma unroll
    for (int i = 0; i < 15; i++) Jp[i] = 0.0f;

    for (int l = lane; l < 150; l += 32) {
        float beta = (l < 100) ? shp[b * 100 + l] : ex[b * 50 + (l - 100)];
        g_pvec[b * KTOT + l] = __float2half_rn(beta);
#pragma unroll
        for (int jk = 0; jk < 15; jk++)
            Jp[jk] = fmaf(sJS[jk * 150 + l], beta, Jp[jk]);
    }
    for (int i = 150 + lane; i < KTOT; i += 32) g_pvec[b * KTOT + i] = __float2half_rn(0.0f);

#pragma unroll
    for (int jk = 0; jk < 15; jk++) {
#pragma unroll
        for (int off = 16; off; off >>= 1)
            Jp[jk] += __shfl_down_sync(0xffffffffu, Jp[jk], off);
    }
    __syncwarp();

    if (lane == 0) {
        float J[5][3];
#pragma unroll
        for (int j = 0; j < 5; j++)
#pragma unroll
            for (int kc = 0; kc < 3; kc++)
                J[j][kc] = Jp[j * 3 + kc] + sJT[j * 3 + kc];

        float R[5][9];
#pragma unroll
        for (int e = 0; e < 9; e++) R[0][e] = (e == 0 || e == 4 || e == 8) ? 1.0f : 0.0f;
        rodr(neck[b * 3 + 0], neck[b * 3 + 1], neck[b * 3 + 2], R[1]);
        rodr(jaw[b * 3 + 0],  jaw[b * 3 + 1],  jaw[b * 3 + 2],  R[2]);
        rodr(eye[b * 6 + 0],  eye[b * 6 + 1],  eye[b * 6 + 2],  R[3]);
        rodr(eye[b * 6 + 3],  eye[b * 6 + 4],  eye[b * 6 + 5],  R[4]);

        __half* pf = &g_pvec[b * KTOT + 150];
#pragma unroll
        for (int j = 1; j < 5; j++)
#pragma unroll
            for (int e = 0; e < 9; e++)
                pf[(j - 1) * 9 + e] = __float2half_rn(R[j][e] - ((e == 0 || e == 4 || e == 8) ? 1.0f : 0.0f));

        float Rg[5][9], tg[5][3];
#pragma unroll
        for (int e = 0; e < 9; e++) Rg[0][e] = R[0][e];
#pragma unroll
        for (int kc = 0; kc < 3; kc++) tg[0][kc] = J[0][kc];
#pragma unroll
        for (int i = 1; i < 5; i++) {
            const int p = (i == 1) ? 0 : 1;
            mm3(Rg[p], R[i], Rg[i]);
            float r0 = J[i][0] - J[p][0], r1 = J[i][1] - J[p][1], r2 = J[i][2] - J[p][2];
#pragma unroll
            for (int r = 0; r < 3; r++)
                tg[i][r] = Rg[p][r * 3 + 0] * r0 + Rg[p][r * 3 + 1] * r1 + Rg[p][r * 3 + 2] * r2 + tg[p][r];
        }
        // batch-PAIR interleaved store: element e of batch b -> [(b>>1)*120 + e*2 + (b&1)]
        float* Am = &g_Amat[(b >> 1) * 120 + (b & 1)];
#pragma unroll
        for (int j = 0; j < 5; j++)
#pragma unroll
            for (int r = 0; r < 3; r++) {
                Am[(j * 12 + r * 4 + 0) * 2] = Rg[j][r * 3 + 0];
                Am[(j * 12 + r * 4 + 1) * 2] = Rg[j][r * 3 + 1];
                Am[(j * 12 + r * 4 + 2) * 2] = Rg[j][r * 3 + 2];
                Am[(j * 12 + r * 4 + 3) * 2] = tg[j][r]
                    - (Rg[j][r * 3 + 0] * J[j][0] + Rg[j][r * 3 + 1] * J[j][1] + Rg[j][r * 3 + 2] * J[j][2]);
            }
    }
}

// ---------------- kernel 2: fp16 mma GEMM + FFMA2 LBS + coalesced stores ----------------
#define STRH 72
#define OFF_A0 0
#define OFF_B0 18432
#define OFF_A1 32256
#define OFF_B1 50688
#define OFF_EAM 64512
#define OFF_EW  95232
#define OFF_EVT 95872
#define DYN_BYTES 96256

__global__ __launch_bounds__(256) void k_main(float* __restrict__ out, int N) {
    extern __shared__ float SM[];
    const uint32_t sbase = smem_u32(SM);

    const int tid = threadIdx.x;
    const int wid = tid >> 5, lane = tid & 31;
    const int q = lane & 3, g = lane >> 2;
    const int wm = wid & 3, wn = wid >> 2;
    const int v0 = blockIdx.x * 32;
    const int b0 = blockIdx.y * 128;

    const uint32_t offA[2] = {OFF_A0, OFF_A1};
    const uint32_t offB[2] = {OFF_B0, OFF_B1};

    auto load_chunk = [&](int ch, int bf) {
#pragma unroll
        for (int i = 0; i < 4; i++) {
            int idx = i * 256 + tid;
            int r = idx >> 3, s = idx & 7;
            int b = b0 + r; if (b >= N) b = N - 1;
            const __half* src = &g_pvec[b * KTOT + ch * KC + s * 8];
            CP_ASYNC16(sbase + offA[bf] + (r * STRH + s * 8) * 2, src);
        }
#pragma unroll
        for (int i = 0; i < 3; i++) {
            int idx = i * 256 + tid;
            int r = idx >> 3, s = idx & 7;
            const __half* src = &g_B[(v0 * 3 + r) * KTOT + ch * KC + s * 8];
            CP_ASYNC16(sbase + offB[bf] + (r * STRH + s * 8) * 2, src);
        }
    };

    // epilogue operand prefetch (padded/aligned sources)
    {
#pragma unroll
        for (int i = 0; i < 8; i++) {
            int seg = i * 256 + tid;
            if (seg < 1920) {
                int gi = b0 * 60 + seg * 4;
                if (gi + 4 > N * 60) gi = N * 60 - 4;
                CP_ASYNC16(sbase + OFF_EAM + seg * 16, &g_Amat[gi]);
            }
        }
        if (tid < 40) CP_ASYNC16(sbase + OFF_EW + tid * 16, &g_Wp[v0 * 5 + tid * 4]);
        if (tid < 24) CP_ASYNC16(sbase + OFF_EVT + tid * 16, &g_VTp[v0 * 3 + tid * 4]);
    }
    load_chunk(0, 0);
    CP_COMMIT();

    float acc[2][6][4];
#pragma unroll
    for (int mi = 0; mi < 2; mi++)
#pragma unroll
        for (int ni = 0; ni < 6; ni++)
#pragma unroll
            for (int r = 0; r < 4; r++) acc[mi][ni][r] = 0.0f;

    for (int ch = 0; ch < NCH; ++ch) {
        const int bf = ch & 1;
        if (ch + 1 < NCH) {
            load_chunk(ch + 1, (ch + 1) & 1);
            CP_COMMIT();
            CP_WAIT(1);
        } else {
            CP_WAIT(0);
        }
        __syncthreads();

        const uint32_t* wA = (const uint32_t*)((const char*)SM + offA[bf]);
        const uint32_t* wB = (const uint32_t*)((const char*)SM + offB[bf]);

#pragma unroll
        for (int s = 0; s < 4; s++) {
            const int kw = s * 8;
            uint32_t a[2][4], b[6][2];
#pragma unroll
            for (int mi = 0; mi < 2; mi++) {
                const uint32_t* p = wA + (wm * 32 + mi * 16 + g) * 36 + kw + q;
                a[mi][0] = p[0];
                a[mi][1] = p[8 * 36];
                a[mi][2] = p[4];
                a[mi][3] = p[8 * 36 + 4];
            }
            const uint32_t* pB = wB + (wn * 48 + g) * 36 + kw + q;
#pragma unroll
            for (int ni = 0; ni < 6; ni++) {
                b[ni][0] = pB[ni * 8 * 36];
                b[ni][1] = pB[ni * 8 * 36 + 4];
            }
#pragma unroll
            for (int mi = 0; mi < 2; mi++)
#pragma unroll
                for (int ni = 0; ni < 6; ni++)
                    mma_f16_16x8x16(acc[mi][ni], a[mi], b[ni]);
        }
        __syncthreads();
    }

    // ---------------- stage GEMM result ----------------
    float* res = SM;                         // 128x100 f32
    const float* sAm = (const float*)((char*)SM + OFF_EAM);  // pair-interleaved
    const float* sW  = (const float*)((char*)SM + OFF_EW);
    const float* sVt = (const float*)((char*)SM + OFF_EVT);
#pragma unroll
    for (int mi = 0; mi < 2; mi++)
#pragma unroll
        for (int ni = 0; ni < 6; ni++)
#pragma unroll
            for (int r = 0; r < 4; r++) {
                int row = wm * 32 + mi * 16 + g + (r >> 1) * 8;
                int col = wn * 48 + ni * 8 + q * 2 + (r & 1);
                res[row * 100 + col] = acc[mi][ni][r];
            }
    __syncthreads();

    // ---------------- FFMA2 LBS, packed across batch pairs ----------------
    const int vg = tid & 7;     // 4 vertices per thread
    const int bg = tid >> 3;    // 4 batches = 2 pairs per thread

    unsigned long long wb[4][5], vtb[4][3];
#pragma unroll
    for (int vi = 0; vi < 4; vi++) {
        int vl = vg * 4 + vi;
#pragma unroll
        for (int j = 0; j < 5; j++) wb[vi][j] = packb(sW[vl * 5 + j]);
#pragma unroll
        for (int m = 0; m < 3; m++) vtb[vi][m] = packb(sVt[vl * 3 + m]);
    }

#pragma unroll
    for (int u = 0; u < 2; u++) {
        const int pl = bg * 2 + u;               // pair index in tile
        const unsigned long long* Ap =
            (const unsigned long long*)&sAm[pl * 120];   // 60 packed pairs
        float* r0p = &res[(2 * pl) * 100];
        float* r1p = &res[(2 * pl + 1) * 100];

        // vp pairs (read all before any write)
        unsigned long long vp2[4][3];
#pragma unroll
        for (int vi = 0; vi < 4; vi++) {
            int c = (vg * 4 + vi) * 3;
#pragma unroll
            for (int m = 0; m < 3; m++)
                vp2[vi][m] = add2(packp(r0p[c + m], r1p[c + m]), vtb[vi][m]);
        }

#pragma unroll
        for (int r = 0; r < 3; r++) {
            unsigned long long A2[5][4];
#pragma unroll
            for (int j = 0; j < 5; j++)
#pragma unroll
                for (int m = 0; m < 4; m++)
                    A2[j][m] = Ap[j * 12 + r * 4 + m];
#pragma unroll
            for (int vi = 0; vi < 4; vi++) {
                unsigned long long s2 = 0ULL;
#pragma unroll
                for (int j = 0; j < 5; j++) {
                    unsigned long long t2 =
                        fma2(A2[j][0], vp2[vi][0],
                        fma2(A2[j][1], vp2[vi][1],
                        fma2(A2[j][2], vp2[vi][2], A2[j][3])));
                    s2 = fma2(wb[vi][j], t2, s2);
                }
                float lo, hi;
                unpk(s2, lo, hi);
                int c = (vg * 4 + vi) * 3 + r;
                r0p[c] = lo;
                r1p[c] = hi;
            }
        }
    }
    __syncthreads();

    // ---------------- coalesced store ----------------
    const int cmax = C3 - v0 * 3;
#pragma unroll
    for (int i = 0; i < 48; i++) {
        int idx = i * 256 + tid;
        int bl = idx / 96, c = idx - bl * 96;
        int b = b0 + bl;
        if (b < N && c < cmax)
            out[(size_t)b * C3 + v0 * 3 + c] = res[bl * 100 + c];
    }
}

// ---------------- launch ----------------
extern "C" void kernel_launch(void* const* d_in, const int* in_sizes, int n_in,
                              void* d_out, int out_size) {
    const float* shp  = (const float*)d_in[0];
    const float* ex   = (const float*)d_in[1];
    const float* neck = (const float*)d_in[2];
    const float* jaw  = (const float*)d_in[3];
    const float* eye  = (const float*)d_in[4];
    const float* vt   = (const float*)d_in[5];
    const float* sd   = (const float*)d_in[6];
    const float* pd   = (const float*)d_in[7];
    const float* jr   = (const float*)d_in[8];
    const float* lw   = (const float*)d_in[9];
    int N = in_sizes[0] / 100;
    if (N > NMAX) N = NMAX;

    static int smem_set = 0;
    if (!smem_set) {
        cudaFuncSetAttribute(k_main, cudaFuncAttributeMaxDynamicSharedMemorySize, DYN_BYTES);
        smem_set = 1;
    }

    k_zero<<<9, 256>>>();
    k_prep<<<32 + (C3PAD * KTOT + 511) / 512, 512>>>(jr, sd, pd, vt, lw);
    k_batch<<<(N + 7) / 8, 256>>>(shp, ex, neck, jaw, eye, N);

    dim3 grid((NV + 31) / 32, (N + 127) / 128);
    k_main<<<grid, 256, DYN_BYTES>>>((float*)d_out, N);
}